// round 9
// baseline (speedup 1.0000x reference)
#include <cuda_runtime.h>
#include <cuda_bf16.h>
#include <math.h>
#include <stdint.h>

#define NNODES 50000
#define MPAD   50048            // 391 * 128
#define EMAX   850048
#define DIM    256
#define COUT   32
#define NEGINF __int_as_float(0xff800000)
#define NPERS  296              // 2 CTAs x 148 SMs

// ---------------- scratch (device globals; no allocation allowed) ----------------
__device__ __align__(128) float g_f  [NNODES * DIM];
__device__ __align__(128) float g_h0 [NNODES * DIM];
__device__ __align__(128) float g_h1 [NNODES * DIM];
__device__ __align__(128) float g_f2 [NNODES * COUT];
__device__ __align__(128) float g_r2 [NNODES * COUT];
__device__ __align__(128) __nv_bfloat16 g_ahi[(size_t)MPAD * DIM];
__device__ __align__(128) __nv_bfloat16 g_alo[(size_t)MPAD * DIM];
__device__ __align__(128) __nv_bfloat16 g_bh0[DIM * DIM];
__device__ __align__(128) __nv_bfloat16 g_bl0[DIM * DIM];
__device__ __align__(128) __nv_bfloat16 g_bh1[DIM * DIM];
__device__ __align__(128) __nv_bfloat16 g_bl1[DIM * DIM];
__device__ __align__(128) __nv_bfloat16 g_bh2[64 * DIM];
__device__ __align__(128) __nv_bfloat16 g_bl2[64 * DIM];
__device__ __align__(128) int   g_deg [NNODES];
__device__ __align__(128) int   g_fill[NNODES];
__device__ __align__(128) int   g_tmp [NNODES];
__device__ __align__(128) int   g_bsum[256];
__device__ __align__(128) int   g_rowptr[NNODES + 1];
__device__ __align__(128) int   g_csrc[EMAX];

// ================= helpers =================
__device__ __forceinline__ uint32_t smem_u32(const void* p) {
    uint32_t a;
    asm("{ .reg .u64 t; cvta.to.shared.u64 t, %1; cvt.u32.u64 %0, t; }" : "=r"(a) : "l"(p));
    return a;
}
__device__ __forceinline__ uint32_t swz(uint32_t off) {
    return off ^ ((off >> 3) & 0x70);   // SW128 for 128B rows
}
#define CP_ASYNC16(dst, src) \
    asm volatile("cp.async.cg.shared.global [%0], [%1], 16;" :: "r"(dst), "l"(src) : "memory")
#define CP_COMMIT()  asm volatile("cp.async.commit_group;" ::: "memory")

__device__ __forceinline__ void ldm_x4(uint32_t* r, uint32_t addr) {
    asm volatile("ldmatrix.sync.aligned.m8n8.x4.shared.b16 {%0,%1,%2,%3}, [%4];"
                 : "=r"(r[0]), "=r"(r[1]), "=r"(r[2]), "=r"(r[3]) : "r"(addr));
}
__device__ __forceinline__ void mma16816(float* d, const uint32_t* a, const uint32_t* b) {
    asm volatile("mma.sync.aligned.m16n8k16.row.col.f32.bf16.bf16.f32 "
                 "{%0,%1,%2,%3}, {%4,%5,%6,%7}, {%8,%9}, {%0,%1,%2,%3};"
                 : "+f"(d[0]), "+f"(d[1]), "+f"(d[2]), "+f"(d[3])
                 : "r"(a[0]), "r"(a[1]), "r"(a[2]), "r"(a[3]), "r"(b[0]), "r"(b[1]));
}

// ================= fused: split_rows(x) + zero deg/fill =================
__global__ void split_x_zero(const float* __restrict__ src, __nv_bfloat16* __restrict__ hi,
                             __nv_bfloat16* __restrict__ lo, int nvalid,
                             int* __restrict__ deg, int* __restrict__ fill, int nNodes) {
    const int splitBlocks = (MPAD * DIM) / 256;   // 50048
    if ((int)blockIdx.x < splitBlocks) {
        int i = blockIdx.x * 256 + threadIdx.x;
        float v = (i < nvalid) ? src[i] : 0.f;
        __nv_bfloat16 h = __float2bfloat16(v);
        hi[i] = h;
        lo[i] = __float2bfloat16(v - __bfloat162float(h));
    } else {
        int i = (blockIdx.x - splitBlocks) * 256 + threadIdx.x;
        if (i < nNodes) { deg[i] = 0; fill[i] = 0; }
    }
}

// ================= plain split (h0, h1) =================
__global__ void split_rows(const float* __restrict__ src, __nv_bfloat16* __restrict__ hi,
                           __nv_bfloat16* __restrict__ lo, int nvalid) {
    int i = blockIdx.x * blockDim.x + threadIdx.x;
    if (i >= MPAD * DIM) return;
    float v = (i < nvalid) ? src[i] : 0.f;
    __nv_bfloat16 h = __float2bfloat16(v);
    hi[i] = h;
    lo[i] = __float2bfloat16(v - __bfloat162float(h));
}

// ================= fused: all weight transposes + degree histogram =================
__global__ void transpose_hist(const float* __restrict__ W0, const float* __restrict__ W1,
                               const float* __restrict__ W2, const float* __restrict__ Wr,
                               __nv_bfloat16* __restrict__ bh0, __nv_bfloat16* __restrict__ bl0,
                               __nv_bfloat16* __restrict__ bh1, __nv_bfloat16* __restrict__ bl1,
                               __nv_bfloat16* __restrict__ bh2, __nv_bfloat16* __restrict__ bl2,
                               const int* __restrict__ dst, int* __restrict__ deg, int E) {
    const int tBlocks = 576;    // 147456 / 256
    if ((int)blockIdx.x < tBlocks) {
        int i = blockIdx.x * 256 + threadIdx.x;
        if (i < 65536) {
            int k = i >> 8, n = i & 255;
            float v = W0[k * 256 + n];
            __nv_bfloat16 h = __float2bfloat16(v);
            bh0[n * 256 + k] = h;
            bl0[n * 256 + k] = __float2bfloat16(v - __bfloat162float(h));
        } else if (i < 131072) {
            int j = i - 65536;
            int k = j >> 8, n = j & 255;
            float v = W1[k * 256 + n];
            __nv_bfloat16 h = __float2bfloat16(v);
            bh1[n * 256 + k] = h;
            bl1[n * 256 + k] = __float2bfloat16(v - __bfloat162float(h));
        } else if (i < 147456) {
            int j = i - 131072;
            int n = j >> 8, k = j & 255;
            float v = (n < 32) ? W2[k * 32 + n] : Wr[k * 32 + (n - 32)];
            __nv_bfloat16 h = __float2bfloat16(v);
            bh2[n * 256 + k] = h;
            bl2[n * 256 + k] = __float2bfloat16(v - __bfloat162float(h));
        }
    } else {
        int i = (blockIdx.x - tBlocks) * 256 + threadIdx.x;
        if (i < E) atomicAdd(&deg[dst[i]], 1);
    }
}

// ================= CSR scan / finalize / scatter =================
__global__ void scan_block(const int* __restrict__ deg, int* __restrict__ incl,
                           int* __restrict__ bsum, int n) {
    __shared__ int sh[256];
    int tid = threadIdx.x;
    int i = blockIdx.x * 256 + tid;
    int v = (i < n) ? deg[i] : 0;
    sh[tid] = v;
    __syncthreads();
    #pragma unroll
    for (int off = 1; off < 256; off <<= 1) {
        int t = (tid >= off) ? sh[tid - off] : 0;
        __syncthreads();
        sh[tid] += t;
        __syncthreads();
    }
    if (i < n) incl[i] = sh[tid];
    if (tid == 255) bsum[blockIdx.x] = sh[255];
}
__global__ void finalize_rowptr(const int* __restrict__ incl, const int* __restrict__ bsum,
                                int* __restrict__ rowptr, int n, int nb) {
    __shared__ int sb[256];
    int tid = threadIdx.x;
    int v = (tid < nb) ? bsum[tid] : 0;
    sb[tid] = v;
    __syncthreads();
    #pragma unroll
    for (int off = 1; off < 256; off <<= 1) {
        int t = (tid >= off) ? sb[tid - off] : 0;
        __syncthreads();
        sb[tid] += t;
        __syncthreads();
    }
    int excl = sb[tid] - v;
    __syncthreads();
    sb[tid] = excl;
    __syncthreads();
    int i = blockIdx.x * blockDim.x + tid;
    if (i < n) rowptr[i + 1] = incl[i] + sb[blockIdx.x];
    if (i == 0) rowptr[0] = 0;
}
__global__ void scatter_edges(const int* __restrict__ src, const int* __restrict__ dst,
                              const int* __restrict__ rowptr, int* __restrict__ fill,
                              int* __restrict__ csrc, int E) {
    int i = blockIdx.x * blockDim.x + threadIdx.x;
    if (i >= E) return;
    int d = dst[i];
    int pos = rowptr[d] + atomicAdd(&fill[d], 1);
    csrc[pos] = src[i];
}

// ================= mma.sync bf16x3 GEMM — persistent, 3-stage cp.async =================
template<int BN, int NT, bool SPLITOUT>
__global__ void __launch_bounds__(256, 2)
gemm_mma(const __nv_bfloat16* __restrict__ Ahi, const __nv_bfloat16* __restrict__ Alo,
         const __nv_bfloat16* __restrict__ Bhi, const __nv_bfloat16* __restrict__ Blo,
         float* __restrict__ C, float* __restrict__ C2, int M, int tiles, int colTiles)
{
    constexpr int ACH = 1024;
    constexpr int BCH = BN * 8;
    constexpr int STAGE = 16384 + BN * 128;
    extern __shared__ char smem[];
    const uint32_t sbase = smem_u32(smem);
    const int tid  = threadIdx.x;
    const int wid  = tid >> 5;
    const int lane = tid & 31;
    const int m0w = (wid & 1) * 64;
    const int n0w = (wid >> 1) * (NT * 8);
    const int aRow = (lane & 15);
    const int aColX = (lane >> 4) << 4;
    const int bRowX = (lane & 7) + ((lane & 16) ? 8 : 0);
    const int bColX = (lane & 8) ? 16 : 0;
    const int g = lane >> 2, tg = lane & 3;

    for (int tile = blockIdx.x; tile < tiles; tile += gridDim.x) {
        const int rowBase = (tile / colTiles) * 128;
        const int colBase = (tile % colTiles) * BN;

        float acc[4][NT][4];
        #pragma unroll
        for (int i = 0; i < 4; i++)
            #pragma unroll
            for (int j = 0; j < NT; j++)
                #pragma unroll
                for (int q = 0; q < 4; q++) acc[i][j][q] = 0.f;

        auto load_stage = [&](int s, int buf) {
            const int k0 = s * 32;
            const uint32_t ab = sbase + buf * STAGE;
            const uint32_t bb = ab + 16384;
            #pragma unroll
            for (int c = tid; c < ACH + BCH; c += 256) {
                if (c < ACH) {
                    int row = c >> 3, sub = c & 7;
                    const __nv_bfloat16* gp = (sub < 4)
                        ? Ahi + ((size_t)(rowBase + row) << 8) + k0 + sub * 8
                        : Alo + ((size_t)(rowBase + row) << 8) + k0 + (sub - 4) * 8;
                    CP_ASYNC16(ab + swz(row * 128 + sub * 16), gp);
                } else {
                    int bc = c - ACH;
                    int row = bc >> 3, sub = bc & 7;
                    const __nv_bfloat16* gp = (sub < 4)
                        ? Bhi + ((size_t)(colBase + row) << 8) + k0 + sub * 8
                        : Blo + ((size_t)(colBase + row) << 8) + k0 + (sub - 4) * 8;
                    CP_ASYNC16(bb + swz(row * 128 + sub * 16), gp);
                }
            }
            CP_COMMIT();
        };

        load_stage(0, 0);
        load_stage(1, 1);
        load_stage(2, 2);

        #pragma unroll
        for (int s = 0; s < 8; s++) {
            if (s <= 5)      asm volatile("cp.async.wait_group 2;" ::: "memory");
            else if (s == 6) asm volatile("cp.async.wait_group 1;" ::: "memory");
            else             asm volatile("cp.async.wait_group 0;" ::: "memory");
            __syncthreads();
            const uint32_t ab = sbase + (s % 3) * STAGE;
            const uint32_t bb = ab + 16384;
            #pragma unroll
            for (int kk = 0; kk < 2; kk++) {
                const int ckh = kk * 32;
                const int ckl = 64 + kk * 32;
                uint32_t ar[4][4], bh[NT / 2][4], bl[NT / 2][4];
                #pragma unroll
                for (int mt = 0; mt < 4; mt++) {
                    int row = m0w + mt * 16 + aRow;
                    ldm_x4(ar[mt], ab + swz(row * 128 + ckh + aColX));
                }
                #pragma unroll
                for (int bt = 0; bt < NT / 2; bt++) {
                    int row = n0w + bt * 16 + bRowX;
                    ldm_x4(bh[bt], bb + swz(row * 128 + ckh + bColX));
                    ldm_x4(bl[bt], bb + swz(row * 128 + ckl + bColX));
                }
                #pragma unroll
                for (int mt = 0; mt < 4; mt++)
                    #pragma unroll
                    for (int nt = 0; nt < NT; nt++) {
                        mma16816(acc[mt][nt], ar[mt], &bh[nt >> 1][(nt & 1) * 2]);
                        mma16816(acc[mt][nt], ar[mt], &bl[nt >> 1][(nt & 1) * 2]);
                    }
                #pragma unroll
                for (int mt = 0; mt < 4; mt++) {
                    int row = m0w + mt * 16 + aRow;
                    ldm_x4(ar[mt], ab + swz(row * 128 + ckl + aColX));
                }
                #pragma unroll
                for (int mt = 0; mt < 4; mt++)
                    #pragma unroll
                    for (int nt = 0; nt < NT; nt++)
                        mma16816(acc[mt][nt], ar[mt], &bh[nt >> 1][(nt & 1) * 2]);
            }
            __syncthreads();
            if (s + 3 < 8) load_stage(s + 3, s % 3);
        }

        #pragma unroll
        for (int mt = 0; mt < 4; mt++) {
            int row0 = rowBase + m0w + mt * 16 + g;
            #pragma unroll
            for (int nt = 0; nt < NT; nt++) {
                int col = n0w + nt * 8 + tg * 2;
                if (!SPLITOUT) {
                    int gc = colBase + col;
                    if (row0 < M)
                        *(float2*)(C + (size_t)row0 * DIM + gc) = make_float2(acc[mt][nt][0], acc[mt][nt][1]);
                    if (row0 + 8 < M)
                        *(float2*)(C + (size_t)(row0 + 8) * DIM + gc) = make_float2(acc[mt][nt][2], acc[mt][nt][3]);
                } else {
                    float* base0 = (col < 32) ? C : C2;
                    int cc = (col < 32) ? col : col - 32;
                    if (row0 < M)
                        *(float2*)(base0 + (size_t)row0 * COUT + cc) = make_float2(acc[mt][nt][0], acc[mt][nt][1]);
                    if (row0 + 8 < M)
                        *(float2*)(base0 + (size_t)(row0 + 8) * COUT + cc) = make_float2(acc[mt][nt][2], acc[mt][nt][3]);
                }
            }
        }
    }
}

// ================= fused GATv2 edge layer (H=4, D=64), warp per node =================
__global__ void __launch_bounds__(256)
gat_layer_h4(const float* __restrict__ f, const int* __restrict__ rowptr,
             const int* __restrict__ csrc, const float* __restrict__ a,
             const float* __restrict__ res, float* __restrict__ out, int n) {
    int warp = (blockIdx.x * blockDim.x + threadIdx.x) >> 5;
    int lane = threadIdx.x & 31;
    if (warp >= n) return;
    const int node = warp;
    const int base = lane * 8;

    float ar[8], fd[8];
    {
        float4 t0 = __ldg((const float4*)(a + base));
        float4 t1 = __ldg((const float4*)(a + base + 4));
        ar[0]=t0.x; ar[1]=t0.y; ar[2]=t0.z; ar[3]=t0.w;
        ar[4]=t1.x; ar[5]=t1.y; ar[6]=t1.z; ar[7]=t1.w;
        const float4* fp = (const float4*)(f + (size_t)node * DIM + base);
        float4 d0 = fp[0], d1 = fp[1];
        fd[0]=d0.x; fd[1]=d0.y; fd[2]=d0.z; fd[3]=d0.w;
        fd[4]=d1.x; fd[5]=d1.y; fd[6]=d1.z; fd[7]=d1.w;
    }

    float acc[8] = {0,0,0,0,0,0,0,0};
    float m = NEGINF, s = 0.f;

    int e0 = rowptr[node], e1 = rowptr[node + 1];
    float4 c0, c1v, p0, p1v;
    {
        int s0 = csrc[e0];
        const float4* fp = (const float4*)(f + (size_t)s0 * DIM + base);
        c0 = fp[0]; c1v = fp[1];
    }
    if (e0 + 1 < e1) {
        int s1 = csrc[e0 + 1];
        const float4* fp = (const float4*)(f + (size_t)s1 * DIM + base);
        p0 = fp[0]; p1v = fp[1];
    }
    for (int e = e0; e < e1; e++) {
        float u[8] = {c0.x, c0.y, c0.z, c0.w, c1v.x, c1v.y, c1v.z, c1v.w};
        c0 = p0; c1v = p1v;
        if (e + 2 < e1) {
            int ns = csrc[e + 2];
            const float4* fp = (const float4*)(f + (size_t)ns * DIM + base);
            p0 = fp[0]; p1v = fp[1];
        }
        float p = 0.f;
        #pragma unroll
        for (int j = 0; j < 8; j++) {
            float v = u[j] + fd[j];
            float lv = v > 0.f ? v : 0.2f * v;
            p = fmaf(lv, ar[j], p);
        }
        p += __shfl_xor_sync(0xffffffffu, p, 1);
        p += __shfl_xor_sync(0xffffffffu, p, 2);
        p += __shfl_xor_sync(0xffffffffu, p, 4);

        float mn = fmaxf(m, p);
        float sc1 = __expf(m - mn);
        float sc2 = __expf(p - mn);
        s = s * sc1 + sc2;
        #pragma unroll
        for (int j = 0; j < 8; j++)
            acc[j] = fmaf(acc[j], sc1, sc2 * u[j]);
        m = mn;
    }
    float inv = 1.0f / s;
    float o[8];
    size_t oidx = (size_t)node * DIM + base;
    #pragma unroll
    for (int j = 0; j < 8; j++) o[j] = acc[j] * inv;
    if (res) {
        const float4* rp = (const float4*)(res + oidx);
        float4 r0 = rp[0], r1 = rp[1];
        o[0]+=r0.x; o[1]+=r0.y; o[2]+=r0.z; o[3]+=r0.w;
        o[4]+=r1.x; o[5]+=r1.y; o[6]+=r1.z; o[7]+=r1.w;
    }
    #pragma unroll
    for (int j = 0; j < 8; j++) o[j] = o[j] > 0.f ? o[j] : expm1f(o[j]);
    float4* op = (float4*)(out + oidx);
    op[0] = make_float4(o[0], o[1], o[2], o[3]);
    op[1] = make_float4(o[4], o[5], o[6], o[7]);
}

// ================= fused final layer (H=1, D=32), warp per node =================
__global__ void __launch_bounds__(256)
gat_layer_h1(const float* __restrict__ f2, const int* __restrict__ rowptr,
             const int* __restrict__ csrc, const float* __restrict__ a,
             const float* __restrict__ r2, float* __restrict__ out, int n) {
    int warp = (blockIdx.x * blockDim.x + threadIdx.x) >> 5;
    int lane = threadIdx.x & 31;
    if (warp >= n) return;
    const int node = warp;

    float ar = __ldg(a + lane);
    float fd = f2[(size_t)node * COUT + lane];

    float acc = 0.f, m = NEGINF, s = 0.f;
    int e0 = rowptr[node], e1 = rowptr[node + 1];
    float cur = f2[(size_t)csrc[e0] * COUT + lane];
    float nxt = 0.f;
    if (e0 + 1 < e1) nxt = f2[(size_t)csrc[e0 + 1] * COUT + lane];
    for (int e = e0; e < e1; e++) {
        float u = cur;
        cur = nxt;
        if (e + 2 < e1) nxt = f2[(size_t)csrc[e + 2] * COUT + lane];
        float v = u + fd;
        float lv = v > 0.f ? v : 0.2f * v;
        float p = lv * ar;
        p += __shfl_xor_sync(0xffffffffu, p, 1);
        p += __shfl_xor_sync(0xffffffffu, p, 2);
        p += __shfl_xor_sync(0xffffffffu, p, 4);
        p += __shfl_xor_sync(0xffffffffu, p, 8);
        p += __shfl_xor_sync(0xffffffffu, p, 16);
        float mn = fmaxf(m, p);
        float sc1 = __expf(m - mn);
        float sc2 = __expf(p - mn);
        s = s * sc1 + sc2;
        acc = fmaf(acc, sc1, sc2 * u);
        m = mn;
    }
    out[(size_t)node * COUT + lane] = acc / s + r2[(size_t)node * COUT + lane];
}

// ================= host =================
extern "C" void kernel_launch(void* const* d_in, const int* in_sizes, int n_in,
                              void* d_out, int out_size) {
    const float* x     = (const float*)d_in[0];
    const int*   src   = (const int*)  d_in[1];
    const int*   dst   = (const int*)  d_in[2];
    const float* W0    = (const float*)d_in[3];
    const float* a0    = (const float*)d_in[4];
    const float* W1    = (const float*)d_in[5];
    const float* a1    = (const float*)d_in[6];
    const float* W2    = (const float*)d_in[7];
    const float* a2    = (const float*)d_in[8];
    const float* Wres2 = (const float*)d_in[9];
    int E = in_sizes[1];
    if (E > EMAX) E = EMAX;

    float *f, *h0, *h1, *f2, *r2;
    __nv_bfloat16 *ahi, *alo, *bh0, *bl0, *bh1, *bl1, *bh2, *bl2;
    int *deg, *fill, *tmp, *bsum, *rowptr, *csrc;
    cudaGetSymbolAddress((void**)&f,    g_f);
    cudaGetSymbolAddress((void**)&h0,   g_h0);
    cudaGetSymbolAddress((void**)&h1,   g_h1);
    cudaGetSymbolAddress((void**)&f2,   g_f2);
    cudaGetSymbolAddress((void**)&r2,   g_r2);
    cudaGetSymbolAddress((void**)&ahi,  g_ahi);
    cudaGetSymbolAddress((void**)&alo,  g_alo);
    cudaGetSymbolAddress((void**)&bh0,  g_bh0);
    cudaGetSymbolAddress((void**)&bl0,  g_bl0);
    cudaGetSymbolAddress((void**)&bh1,  g_bh1);
    cudaGetSymbolAddress((void**)&bl1,  g_bl1);
    cudaGetSymbolAddress((void**)&bh2,  g_bh2);
    cudaGetSymbolAddress((void**)&bl2,  g_bl2);
    cudaGetSymbolAddress((void**)&deg,  g_deg);
    cudaGetSymbolAddress((void**)&fill, g_fill);
    cudaGetSymbolAddress((void**)&tmp,  g_tmp);
    cudaGetSymbolAddress((void**)&bsum, g_bsum);
    cudaGetSymbolAddress((void**)&rowptr, g_rowptr);
    cudaGetSymbolAddress((void**)&csrc, g_csrc);

    const int SMEM_BIG   = 3 * (16384 + 128 * 128);  // 98304
    const int SMEM_SMALL = 3 * (16384 + 64 * 128);   // 73728
    static int smem_set = 0;
    if (!smem_set) {
        cudaFuncSetAttribute((const void*)gemm_mma<128, 4, false>,
                             cudaFuncAttributeMaxDynamicSharedMemorySize, SMEM_BIG);
        cudaFuncSetAttribute((const void*)gemm_mma<64, 2, true>,
                             cudaFuncAttributeMaxDynamicSharedMemorySize, SMEM_SMALL);
        smem_set = 1;
    }

    const int TPB = 256;
    const int NB = (NNODES + 255) / 256;   // 196
    const int EB = (E + TPB - 1) / TPB;
    const int nodeWarpBlocks = (NNODES * 32 + TPB - 1) / TPB;
    const int splitBlocks = (MPAD * DIM + TPB - 1) / TPB;
    const int bigTiles = 2 * (MPAD / 128);   // 782
    const int smallTiles = MPAD / 128;       // 391

    // ---- prep (fused) ----
    split_x_zero<<<splitBlocks + NB, TPB>>>(x, ahi, alo, NNODES * DIM, deg, fill, NNODES); // 1
    transpose_hist<<<576 + EB, TPB>>>(W0, W1, W2, Wres2, bh0, bl0, bh1, bl1, bh2, bl2,
                                      dst, deg, E);                                        // 2
    gemm_mma<128, 4, false><<<NPERS, TPB, SMEM_BIG>>>(ahi, alo, bh0, bl0, f, nullptr,
                                                      NNODES, bigTiles, 2);                // 3

    // ---- CSR finish ----
    scan_block<<<NB, TPB>>>(deg, tmp, bsum, NNODES);                                       // 4
    finalize_rowptr<<<NB, TPB>>>(tmp, bsum, rowptr, NNODES, NB);                           // 5
    scatter_edges<<<EB, TPB>>>(src, dst, rowptr, fill, csrc, E);                           // 6

    // ---- layer 0 edge phase ----
    gat_layer_h4<<<nodeWarpBlocks, TPB>>>(f, rowptr, csrc, a0, nullptr, h0, NNODES);       // 7

    // ---- layer 1 ----
    split_rows<<<splitBlocks, TPB>>>(h0, ahi, alo, NNODES * DIM);                          // 8
    gemm_mma<128, 4, false><<<NPERS, TPB, SMEM_BIG>>>(ahi, alo, bh1, bl1, f, nullptr,
                                                      NNODES, bigTiles, 2);                // 9
    gat_layer_h4<<<nodeWarpBlocks, TPB>>>(f, rowptr, csrc, a1, h0, h1, NNODES);            // 10

    // ---- layer 2 ----
    split_rows<<<splitBlocks, TPB>>>(h1, ahi, alo, NNODES * DIM);                          // 11
    gemm_mma<64, 2, true><<<NPERS, TPB, SMEM_SMALL>>>(ahi, alo, bh2, bl2, f2, r2,
                                                      NNODES, smallTiles, 1);              // 12
    gat_layer_h1<<<nodeWarpBlocks, TPB>>>(f2, rowptr, csrc, a2, r2, (float*)d_out, NNODES);// 13
}

// round 10
// speedup vs baseline: 1.0486x; 1.0486x over previous
#include <cuda_runtime.h>
#include <cuda_bf16.h>
#include <math.h>
#include <stdint.h>

#define NNODES 50000
#define MPAD   50048            // 391 * 128
#define EMAX   850048
#define DIM    256
#define COUT   32
#define NEGINF __int_as_float(0xff800000)

// ---------------- scratch (device globals; no allocation allowed) ----------------
__device__ __align__(128) float g_f  [NNODES * DIM];
__device__ __align__(128) float g_h0 [NNODES * DIM];
__device__ __align__(128) float g_h1 [NNODES * DIM];
__device__ __align__(128) float g_f2 [NNODES * COUT];
__device__ __align__(128) float g_r2 [NNODES * COUT];
__device__ __align__(128) __nv_bfloat16 g_ahi[(size_t)MPAD * DIM];
__device__ __align__(128) __nv_bfloat16 g_alo[(size_t)MPAD * DIM];
__device__ __align__(128) __nv_bfloat16 g_bh0[DIM * DIM];
__device__ __align__(128) __nv_bfloat16 g_bl0[DIM * DIM];
__device__ __align__(128) __nv_bfloat16 g_bh1[DIM * DIM];
__device__ __align__(128) __nv_bfloat16 g_bl1[DIM * DIM];
__device__ __align__(128) __nv_bfloat16 g_bh2[64 * DIM];
__device__ __align__(128) __nv_bfloat16 g_bl2[64 * DIM];
__device__ __align__(128) int   g_deg [NNODES];
__device__ __align__(128) int   g_fill[NNODES];
__device__ __align__(128) int   g_tmp [NNODES];
__device__ __align__(128) int   g_bsum[256];
__device__ __align__(128) int   g_rowptr[NNODES + 1];
__device__ __align__(128) int   g_csrc[EMAX];

// ================= helpers =================
__device__ __forceinline__ uint32_t smem_u32(const void* p) {
    uint32_t a;
    asm("{ .reg .u64 t; cvta.to.shared.u64 t, %1; cvt.u32.u64 %0, t; }" : "=r"(a) : "l"(p));
    return a;
}
__device__ __forceinline__ uint32_t swz(uint32_t off) {
    return off ^ ((off >> 3) & 0x70);   // SW128 for 128B rows
}
#define CP_ASYNC16(dst, src) \
    asm volatile("cp.async.cg.shared.global [%0], [%1], 16;" :: "r"(dst), "l"(src) : "memory")
#define CP_COMMIT()  asm volatile("cp.async.commit_group;" ::: "memory")

__device__ __forceinline__ void ldm_x4(uint32_t* r, uint32_t addr) {
    asm volatile("ldmatrix.sync.aligned.m8n8.x4.shared.b16 {%0,%1,%2,%3}, [%4];"
                 : "=r"(r[0]), "=r"(r[1]), "=r"(r[2]), "=r"(r[3]) : "r"(addr));
}
__device__ __forceinline__ void mma16816(float* d, const uint32_t* a, const uint32_t* b) {
    asm volatile("mma.sync.aligned.m16n8k16.row.col.f32.bf16.bf16.f32 "
                 "{%0,%1,%2,%3}, {%4,%5,%6,%7}, {%8,%9}, {%0,%1,%2,%3};"
                 : "+f"(d[0]), "+f"(d[1]), "+f"(d[2]), "+f"(d[3])
                 : "r"(a[0]), "r"(a[1]), "r"(a[2]), "r"(a[3]), "r"(b[0]), "r"(b[1]));
}

// ================= CSR build =================
__global__ void zero_ints(int* __restrict__ a, int* __restrict__ b, int n) {
    int i = blockIdx.x * blockDim.x + threadIdx.x;
    if (i < n) { a[i] = 0; b[i] = 0; }
}
__global__ void hist_deg(const int* __restrict__ dst, int* __restrict__ deg, int E) {
    int i = blockIdx.x * blockDim.x + threadIdx.x;
    if (i < E) atomicAdd(&deg[dst[i]], 1);
}
__global__ void scan_block(const int* __restrict__ deg, int* __restrict__ incl,
                           int* __restrict__ bsum, int n) {
    __shared__ int sh[256];
    int tid = threadIdx.x;
    int i = blockIdx.x * 256 + tid;
    int v = (i < n) ? deg[i] : 0;
    sh[tid] = v;
    __syncthreads();
    #pragma unroll
    for (int off = 1; off < 256; off <<= 1) {
        int t = (tid >= off) ? sh[tid - off] : 0;
        __syncthreads();
        sh[tid] += t;
        __syncthreads();
    }
    if (i < n) incl[i] = sh[tid];
    if (tid == 255) bsum[blockIdx.x] = sh[255];
}
// merged: scan of block sums (in smem, redone per block) + rowptr finalize
__global__ void finalize_rowptr(const int* __restrict__ incl, const int* __restrict__ bsum,
                                int* __restrict__ rowptr, int n, int nb) {
    __shared__ int sb[256];
    int tid = threadIdx.x;
    int v = (tid < nb) ? bsum[tid] : 0;
    sb[tid] = v;
    __syncthreads();
    #pragma unroll
    for (int off = 1; off < 256; off <<= 1) {
        int t = (tid >= off) ? sb[tid - off] : 0;
        __syncthreads();
        sb[tid] += t;
        __syncthreads();
    }
    int excl = sb[tid] - v;
    __syncthreads();
    sb[tid] = excl;
    __syncthreads();
    int i = blockIdx.x * blockDim.x + tid;
    if (i < n) rowptr[i + 1] = incl[i] + sb[blockIdx.x];
    if (i == 0) rowptr[0] = 0;
}
__global__ void scatter_edges(const int* __restrict__ src, const int* __restrict__ dst,
                              const int* __restrict__ rowptr, int* __restrict__ fill,
                              int* __restrict__ csrc, int E) {
    int i = blockIdx.x * blockDim.x + threadIdx.x;
    if (i >= E) return;
    int d = dst[i];
    int pos = rowptr[d] + atomicAdd(&fill[d], 1);
    csrc[pos] = src[i];
}

// ================= fp32 -> bf16 hi/lo split =================
__global__ void split_rows(const float* __restrict__ src, __nv_bfloat16* __restrict__ hi,
                           __nv_bfloat16* __restrict__ lo, int nvalid) {
    int i = blockIdx.x * blockDim.x + threadIdx.x;
    if (i >= MPAD * DIM) return;
    float v = (i < nvalid) ? src[i] : 0.f;
    __nv_bfloat16 h = __float2bfloat16(v);
    hi[i] = h;
    lo[i] = __float2bfloat16(v - __bfloat162float(h));
}

// all three layers' weight transposes + splits in one kernel
__global__ void transpose_all(const float* __restrict__ W0, const float* __restrict__ W1,
                              const float* __restrict__ W2, const float* __restrict__ Wr,
                              __nv_bfloat16* __restrict__ bh0, __nv_bfloat16* __restrict__ bl0,
                              __nv_bfloat16* __restrict__ bh1, __nv_bfloat16* __restrict__ bl1,
                              __nv_bfloat16* __restrict__ bh2, __nv_bfloat16* __restrict__ bl2) {
    int i = blockIdx.x * blockDim.x + threadIdx.x;
    if (i < 65536) {
        int k = i >> 8, n = i & 255;
        float v = W0[k * 256 + n];
        __nv_bfloat16 h = __float2bfloat16(v);
        bh0[n * 256 + k] = h;
        bl0[n * 256 + k] = __float2bfloat16(v - __bfloat162float(h));
    } else if (i < 131072) {
        int j = i - 65536;
        int k = j >> 8, n = j & 255;
        float v = W1[k * 256 + n];
        __nv_bfloat16 h = __float2bfloat16(v);
        bh1[n * 256 + k] = h;
        bl1[n * 256 + k] = __float2bfloat16(v - __bfloat162float(h));
    } else if (i < 147456) {
        int j = i - 131072;
        int n = j >> 8, k = j & 255;
        float v = (n < 32) ? W2[k * 32 + n] : Wr[k * 32 + (n - 32)];
        __nv_bfloat16 h = __float2bfloat16(v);
        bh2[n * 256 + k] = h;
        bl2[n * 256 + k] = __float2bfloat16(v - __bfloat162float(h));
    }
}

// ================= mma.sync bf16x3 GEMM — 3-stage cp.async pipeline =================
template<int BN, int NT, bool SPLITOUT>
__global__ void __launch_bounds__(256, 2)
gemm_mma(const __nv_bfloat16* __restrict__ Ahi, const __nv_bfloat16* __restrict__ Alo,
         const __nv_bfloat16* __restrict__ Bhi, const __nv_bfloat16* __restrict__ Blo,
         float* __restrict__ C, float* __restrict__ C2, int M)
{
    constexpr int ACH = 1024;
    constexpr int BCH = BN * 8;
    constexpr int STAGE = 16384 + BN * 128;
    extern __shared__ char smem[];
    const uint32_t sbase = smem_u32(smem);
    const int tid  = threadIdx.x;
    const int wid  = tid >> 5;
    const int lane = tid & 31;
    const int rowBase = blockIdx.y * 128;
    const int colBase = blockIdx.x * BN;
    const int m0w = (wid & 1) * 64;
    const int n0w = (wid >> 1) * (NT * 8);

    float acc[4][NT][4];
    #pragma unroll
    for (int i = 0; i < 4; i++)
        #pragma unroll
        for (int j = 0; j < NT; j++)
            #pragma unroll
            for (int q = 0; q < 4; q++) acc[i][j][q] = 0.f;

    auto load_stage = [&](int s, int buf) {
        const int k0 = s * 32;
        const uint32_t ab = sbase + buf * STAGE;
        const uint32_t bb = ab + 16384;
        #pragma unroll
        for (int c = tid; c < ACH + BCH; c += 256) {
            if (c < ACH) {
                int row = c >> 3, sub = c & 7;
                const __nv_bfloat16* g = (sub < 4)
                    ? Ahi + ((size_t)(rowBase + row) << 8) + k0 + sub * 8
                    : Alo + ((size_t)(rowBase + row) << 8) + k0 + (sub - 4) * 8;
                CP_ASYNC16(ab + swz(row * 128 + sub * 16), g);
            } else {
                int bc = c - ACH;
                int row = bc >> 3, sub = bc & 7;
                const __nv_bfloat16* g = (sub < 4)
                    ? Bhi + ((size_t)(colBase + row) << 8) + k0 + sub * 8
                    : Blo + ((size_t)(colBase + row) << 8) + k0 + (sub - 4) * 8;
                CP_ASYNC16(bb + swz(row * 128 + sub * 16), g);
            }
        }
        CP_COMMIT();
    };

    load_stage(0, 0);
    load_stage(1, 1);
    load_stage(2, 2);

    const int aRow = (lane & 15);
    const int aColX = (lane >> 4) << 4;
    const int bRowX = (lane & 7) + ((lane & 16) ? 8 : 0);
    const int bColX = (lane & 8) ? 16 : 0;

    #pragma unroll
    for (int s = 0; s < 8; s++) {
        if (s <= 5)      asm volatile("cp.async.wait_group 2;" ::: "memory");
        else if (s == 6) asm volatile("cp.async.wait_group 1;" ::: "memory");
        else             asm volatile("cp.async.wait_group 0;" ::: "memory");
        __syncthreads();
        const uint32_t ab = sbase + (s % 3) * STAGE;
        const uint32_t bb = ab + 16384;
        #pragma unroll
        for (int kk = 0; kk < 2; kk++) {
            const int ckh = kk * 32;
            const int ckl = 64 + kk * 32;
            uint32_t ar[4][4], bh[NT / 2][4], bl[NT / 2][4];
            #pragma unroll
            for (int mt = 0; mt < 4; mt++) {
                int row = m0w + mt * 16 + aRow;
                ldm_x4(ar[mt], ab + swz(row * 128 + ckh + aColX));
            }
            #pragma unroll
            for (int bt = 0; bt < NT / 2; bt++) {
                int row = n0w + bt * 16 + bRowX;
                ldm_x4(bh[bt], bb + swz(row * 128 + ckh + bColX));
                ldm_x4(bl[bt], bb + swz(row * 128 + ckl + bColX));
            }
            #pragma unroll
            for (int mt = 0; mt < 4; mt++)
                #pragma unroll
                for (int nt = 0; nt < NT; nt++) {
                    mma16816(acc[mt][nt], ar[mt], &bh[nt >> 1][(nt & 1) * 2]);
                    mma16816(acc[mt][nt], ar[mt], &bl[nt >> 1][(nt & 1) * 2]);
                }
            #pragma unroll
            for (int mt = 0; mt < 4; mt++) {
                int row = m0w + mt * 16 + aRow;
                ldm_x4(ar[mt], ab + swz(row * 128 + ckl + aColX));
            }
            #pragma unroll
            for (int mt = 0; mt < 4; mt++)
                #pragma unroll
                for (int nt = 0; nt < NT; nt++)
                    mma16816(acc[mt][nt], ar[mt], &bh[nt >> 1][(nt & 1) * 2]);
        }
        __syncthreads();
        if (s + 3 < 8) load_stage(s + 3, s % 3);
    }

    const int g = lane >> 2, tg = lane & 3;
    #pragma unroll
    for (int mt = 0; mt < 4; mt++) {
        int row0 = rowBase + m0w + mt * 16 + g;
        #pragma unroll
        for (int nt = 0; nt < NT; nt++) {
            int col = n0w + nt * 8 + tg * 2;
            if (!SPLITOUT) {
                int gc = colBase + col;
                if (row0 < M)
                    *(float2*)(C + (size_t)row0 * DIM + gc) = make_float2(acc[mt][nt][0], acc[mt][nt][1]);
                if (row0 + 8 < M)
                    *(float2*)(C + (size_t)(row0 + 8) * DIM + gc) = make_float2(acc[mt][nt][2], acc[mt][nt][3]);
            } else {
                float* base0 = (col < 32) ? C : C2;
                int cc = (col < 32) ? col : col - 32;
                if (row0 < M)
                    *(float2*)(base0 + (size_t)row0 * COUT + cc) = make_float2(acc[mt][nt][0], acc[mt][nt][1]);
                if (row0 + 8 < M)
                    *(float2*)(base0 + (size_t)(row0 + 8) * COUT + cc) = make_float2(acc[mt][nt][2], acc[mt][nt][3]);
            }
        }
    }
}

// ================= fused GATv2 edge layer (H=4, D=64), warp per node =================
__global__ void __launch_bounds__(256)
gat_layer_h4(const float* __restrict__ f, const int* __restrict__ rowptr,
             const int* __restrict__ csrc, const float* __restrict__ a,
             const float* __restrict__ res, float* __restrict__ out, int n) {
    int warp = (blockIdx.x * blockDim.x + threadIdx.x) >> 5;
    int lane = threadIdx.x & 31;
    if (warp >= n) return;
    const int node = warp;
    const int base = lane * 8;

    float ar[8], fd[8];
    {
        float4 t0 = __ldg((const float4*)(a + base));
        float4 t1 = __ldg((const float4*)(a + base + 4));
        ar[0]=t0.x; ar[1]=t0.y; ar[2]=t0.z; ar[3]=t0.w;
        ar[4]=t1.x; ar[5]=t1.y; ar[6]=t1.z; ar[7]=t1.w;
        const float4* fp = (const float4*)(f + (size_t)node * DIM + base);
        float4 d0 = fp[0], d1 = fp[1];
        fd[0]=d0.x; fd[1]=d0.y; fd[2]=d0.z; fd[3]=d0.w;
        fd[4]=d1.x; fd[5]=d1.y; fd[6]=d1.z; fd[7]=d1.w;
    }

    float acc[8] = {0,0,0,0,0,0,0,0};
    float m = NEGINF, s = 0.f;

    int e0 = rowptr[node], e1 = rowptr[node + 1];
    float4 c0, c1v, p0, p1v;
    {
        int s0 = csrc[e0];
        const float4* fp = (const float4*)(f + (size_t)s0 * DIM + base);
        c0 = fp[0]; c1v = fp[1];
    }
    if (e0 + 1 < e1) {
        int s1 = csrc[e0 + 1];
        const float4* fp = (const float4*)(f + (size_t)s1 * DIM + base);
        p0 = fp[0]; p1v = fp[1];
    }
    for (int e = e0; e < e1; e++) {
        float u[8] = {c0.x, c0.y, c0.z, c0.w, c1v.x, c1v.y, c1v.z, c1v.w};
        c0 = p0; c1v = p1v;
        if (e + 2 < e1) {
            int ns = csrc[e + 2];
            const float4* fp = (const float4*)(f + (size_t)ns * DIM + base);
            p0 = fp[0]; p1v = fp[1];
        }
        float p = 0.f;
        #pragma unroll
        for (int j = 0; j < 8; j++) {
            float v = u[j] + fd[j];
            float lv = v > 0.f ? v : 0.2f * v;
            p = fmaf(lv, ar[j], p);
        }
        p += __shfl_xor_sync(0xffffffffu, p, 1);
        p += __shfl_xor_sync(0xffffffffu, p, 2);
        p += __shfl_xor_sync(0xffffffffu, p, 4);

        float mn = fmaxf(m, p);
        float sc1 = __expf(m - mn);
        float sc2 = __expf(p - mn);
        s = s * sc1 + sc2;
        #pragma unroll
        for (int j = 0; j < 8; j++)
            acc[j] = fmaf(acc[j], sc1, sc2 * u[j]);
        m = mn;
    }
    float inv = 1.0f / s;
    float o[8];
    size_t oidx = (size_t)node * DIM + base;
    #pragma unroll
    for (int j = 0; j < 8; j++) o[j] = acc[j] * inv;
    if (res) {
        const float4* rp = (const float4*)(res + oidx);
        float4 r0 = rp[0], r1 = rp[1];
        o[0]+=r0.x; o[1]+=r0.y; o[2]+=r0.z; o[3]+=r0.w;
        o[4]+=r1.x; o[5]+=r1.y; o[6]+=r1.z; o[7]+=r1.w;
    }
    #pragma unroll
    for (int j = 0; j < 8; j++) o[j] = o[j] > 0.f ? o[j] : expm1f(o[j]);
    float4* op = (float4*)(out + oidx);
    op[0] = make_float4(o[0], o[1], o[2], o[3]);
    op[1] = make_float4(o[4], o[5], o[6], o[7]);
}

// ================= fused final layer (H=1, D=32), warp per node =================
__global__ void __launch_bounds__(256)
gat_layer_h1(const float* __restrict__ f2, const int* __restrict__ rowptr,
             const int* __restrict__ csrc, const float* __restrict__ a,
             const float* __restrict__ r2, float* __restrict__ out, int n) {
    int warp = (blockIdx.x * blockDim.x + threadIdx.x) >> 5;
    int lane = threadIdx.x & 31;
    if (warp >= n) return;
    const int node = warp;

    float ar = __ldg(a + lane);
    float fd = f2[(size_t)node * COUT + lane];

    float acc = 0.f, m = NEGINF, s = 0.f;
    int e0 = rowptr[node], e1 = rowptr[node + 1];
    float cur = f2[(size_t)csrc[e0] * COUT + lane];
    float nxt = 0.f;
    if (e0 + 1 < e1) nxt = f2[(size_t)csrc[e0 + 1] * COUT + lane];
    for (int e = e0; e < e1; e++) {
        float u = cur;
        cur = nxt;
        if (e + 2 < e1) nxt = f2[(size_t)csrc[e + 2] * COUT + lane];
        float v = u + fd;
        float lv = v > 0.f ? v : 0.2f * v;
        float p = lv * ar;
        p += __shfl_xor_sync(0xffffffffu, p, 1);
        p += __shfl_xor_sync(0xffffffffu, p, 2);
        p += __shfl_xor_sync(0xffffffffu, p, 4);
        p += __shfl_xor_sync(0xffffffffu, p, 8);
        p += __shfl_xor_sync(0xffffffffu, p, 16);
        float mn = fmaxf(m, p);
        float sc1 = __expf(m - mn);
        float sc2 = __expf(p - mn);
        s = s * sc1 + sc2;
        acc = fmaf(acc, sc1, sc2 * u);
        m = mn;
    }
    out[(size_t)node * COUT + lane] = acc / s + r2[(size_t)node * COUT + lane];
}

// ================= host =================
extern "C" void kernel_launch(void* const* d_in, const int* in_sizes, int n_in,
                              void* d_out, int out_size) {
    const float* x     = (const float*)d_in[0];
    const int*   src   = (const int*)  d_in[1];
    const int*   dst   = (const int*)  d_in[2];
    const float* W0    = (const float*)d_in[3];
    const float* a0    = (const float*)d_in[4];
    const float* W1    = (const float*)d_in[5];
    const float* a1    = (const float*)d_in[6];
    const float* W2    = (const float*)d_in[7];
    const float* a2    = (const float*)d_in[8];
    const float* Wres2 = (const float*)d_in[9];
    int E = in_sizes[1];
    if (E > EMAX) E = EMAX;

    float *f, *h0, *h1, *f2, *r2;
    __nv_bfloat16 *ahi, *alo, *bh0, *bl0, *bh1, *bl1, *bh2, *bl2;
    int *deg, *fill, *tmp, *bsum, *rowptr, *csrc;
    cudaGetSymbolAddress((void**)&f,    g_f);
    cudaGetSymbolAddress((void**)&h0,   g_h0);
    cudaGetSymbolAddress((void**)&h1,   g_h1);
    cudaGetSymbolAddress((void**)&f2,   g_f2);
    cudaGetSymbolAddress((void**)&r2,   g_r2);
    cudaGetSymbolAddress((void**)&ahi,  g_ahi);
    cudaGetSymbolAddress((void**)&alo,  g_alo);
    cudaGetSymbolAddress((void**)&bh0,  g_bh0);
    cudaGetSymbolAddress((void**)&bl0,  g_bl0);
    cudaGetSymbolAddress((void**)&bh1,  g_bh1);
    cudaGetSymbolAddress((void**)&bl1,  g_bl1);
    cudaGetSymbolAddress((void**)&bh2,  g_bh2);
    cudaGetSymbolAddress((void**)&bl2,  g_bl2);
    cudaGetSymbolAddress((void**)&deg,  g_deg);
    cudaGetSymbolAddress((void**)&fill, g_fill);
    cudaGetSymbolAddress((void**)&tmp,  g_tmp);
    cudaGetSymbolAddress((void**)&bsum, g_bsum);
    cudaGetSymbolAddress((void**)&rowptr, g_rowptr);
    cudaGetSymbolAddress((void**)&csrc, g_csrc);

    const int SMEM_BIG   = 3 * (16384 + 128 * 128);  // 98304
    const int SMEM_SMALL = 3 * (16384 + 64 * 128);   // 73728
    static int inited = 0;
    static cudaStream_t s2;
    static cudaEvent_t evFork, evJoin;
    if (!inited) {
        cudaFuncSetAttribute((const void*)gemm_mma<128, 4, false>,
                             cudaFuncAttributeMaxDynamicSharedMemorySize, SMEM_BIG);
        cudaFuncSetAttribute((const void*)gemm_mma<64, 2, true>,
                             cudaFuncAttributeMaxDynamicSharedMemorySize, SMEM_SMALL);
        cudaStreamCreateWithFlags(&s2, cudaStreamNonBlocking);
        cudaEventCreateWithFlags(&evFork, cudaEventDisableTiming);
        cudaEventCreateWithFlags(&evJoin, cudaEventDisableTiming);
        inited = 1;
    }

    const int TPB = 256;
    const int NB = (NNODES + 255) / 256;   // 196
    const int EB = (E + TPB - 1) / TPB;
    const int nodeWarpBlocks = (NNODES * 32 + TPB - 1) / TPB;
    const int splitBlocks = (MPAD * DIM + TPB - 1) / TPB;
    dim3 gemmGrid(2, MPAD / 128);
    dim3 gemmGridS(1, MPAD / 128);

    // ---- fork: CSR build chain runs on s2, concurrent with split/transpose/GEMM-0 ----
    cudaEventRecord(evFork, 0);
    cudaStreamWaitEvent(s2, evFork, 0);
    zero_ints<<<NB, TPB, 0, s2>>>(deg, fill, NNODES);
    hist_deg<<<EB, TPB, 0, s2>>>(dst, deg, E);
    scan_block<<<NB, TPB, 0, s2>>>(deg, tmp, bsum, NNODES);
    finalize_rowptr<<<NB, TPB, 0, s2>>>(tmp, bsum, rowptr, NNODES, NB);
    scatter_edges<<<EB, TPB, 0, s2>>>(src, dst, rowptr, fill, csrc, E);
    cudaEventRecord(evJoin, s2);

    // ---- main stream: layer-0 projection ----
    split_rows<<<splitBlocks, TPB>>>(x, ahi, alo, NNODES * DIM);
    transpose_all<<<(147456 + TPB - 1) / TPB, TPB>>>(W0, W1, W2, Wres2,
                                                     bh0, bl0, bh1, bl1, bh2, bl2);
    gemm_mma<128, 4, false><<<gemmGrid, TPB, SMEM_BIG>>>(ahi, alo, bh0, bl0, f, nullptr, NNODES);

    // ---- join: GAT needs CSR + f ----
    cudaStreamWaitEvent(0, evJoin, 0);
    gat_layer_h4<<<nodeWarpBlocks, TPB>>>(f, rowptr, csrc, a0, nullptr, h0, NNODES);

    // ---- layer 1 ----
    split_rows<<<splitBlocks, TPB>>>(h0, ahi, alo, NNODES * DIM);
    gemm_mma<128, 4, false><<<gemmGrid, TPB, SMEM_BIG>>>(ahi, alo, bh1, bl1, f, nullptr, NNODES);
    gat_layer_h4<<<nodeWarpBlocks, TPB>>>(f, rowptr, csrc, a1, h0, h1, NNODES);

    // ---- layer 2 ----
    split_rows<<<splitBlocks, TPB>>>(h1, ahi, alo, NNODES * DIM);
    gemm_mma<64, 2, true><<<gemmGridS, TPB, SMEM_SMALL>>>(ahi, alo, bh2, bl2, f2, r2, NNODES);
    gat_layer_h1<<<nodeWarpBlocks, TPB>>>(f2, rowptr, csrc, a2, r2, (float*)d_out, NNODES);
}

// round 11
// speedup vs baseline: 1.1517x; 1.0983x over previous
#include <cuda_runtime.h>
#include <cuda_bf16.h>
#include <math.h>
#include <stdint.h>

#define NNODES 50000
#define MPAD   50048            // 391 * 128
#define EMAX   850048
#define DIM    256
#define COUT   32
#define NEGINF __int_as_float(0xff800000)

// ---------------- scratch (device globals; no allocation allowed) ----------------
__device__ __align__(128) float g_f  [NNODES * DIM];
__device__ __align__(128) float g_h0 [NNODES * DIM];
__device__ __align__(128) float g_f2 [NNODES * COUT];
__device__ __align__(128) float g_r2 [NNODES * COUT];
__device__ __align__(128) __nv_bfloat16 g_ahi[(size_t)MPAD * DIM];
__device__ __align__(128) __nv_bfloat16 g_alo[(size_t)MPAD * DIM];
__device__ __align__(128) __nv_bfloat16 g_bh0[DIM * DIM];
__device__ __align__(128) __nv_bfloat16 g_bl0[DIM * DIM];
__device__ __align__(128) __nv_bfloat16 g_bh1[DIM * DIM];
__device__ __align__(128) __nv_bfloat16 g_bl1[DIM * DIM];
__device__ __align__(128) __nv_bfloat16 g_bh2[64 * DIM];
__device__ __align__(128) __nv_bfloat16 g_bl2[64 * DIM];
__device__ __align__(128) int   g_deg [NNODES];
__device__ __align__(128) int   g_fill[NNODES];
__device__ __align__(128) int   g_tmp [NNODES];
__device__ __align__(128) int   g_bsum[256];
__device__ __align__(128) int   g_rowptr[NNODES + 1];
__device__ __align__(128) int   g_csrc[EMAX];

// ================= helpers =================
__device__ __forceinline__ uint32_t smem_u32(const void* p) {
    uint32_t a;
    asm("{ .reg .u64 t; cvta.to.shared.u64 t, %1; cvt.u32.u64 %0, t; }" : "=r"(a) : "l"(p));
    return a;
}
__device__ __forceinline__ uint32_t swz(uint32_t off) {
    return off ^ ((off >> 3) & 0x70);   // SW128 for 128B rows
}
#define CP_ASYNC16(dst, src) \
    asm volatile("cp.async.cg.shared.global [%0], [%1], 16;" :: "r"(dst), "l"(src) : "memory")
#define CP_COMMIT()  asm volatile("cp.async.commit_group;" ::: "memory")

__device__ __forceinline__ void ldm_x4(uint32_t* r, uint32_t addr) {
    asm volatile("ldmatrix.sync.aligned.m8n8.x4.shared.b16 {%0,%1,%2,%3}, [%4];"
                 : "=r"(r[0]), "=r"(r[1]), "=r"(r[2]), "=r"(r[3]) : "r"(addr));
}
__device__ __forceinline__ void mma16816(float* d, const uint32_t* a, const uint32_t* b) {
    asm volatile("mma.sync.aligned.m16n8k16.row.col.f32.bf16.bf16.f32 "
                 "{%0,%1,%2,%3}, {%4,%5,%6,%7}, {%8,%9}, {%0,%1,%2,%3};"
                 : "+f"(d[0]), "+f"(d[1]), "+f"(d[2]), "+f"(d[3])
                 : "r"(a[0]), "r"(a[1]), "r"(a[2]), "r"(a[3]), "r"(b[0]), "r"(b[1]));
}

// ================= CSR build =================
__global__ void zero_ints(int* __restrict__ a, int* __restrict__ b, int n) {
    int i = blockIdx.x * blockDim.x + threadIdx.x;
    if (i < n) { a[i] = 0; b[i] = 0; }
}
__global__ void hist_deg(const int* __restrict__ dst, int* __restrict__ deg, int E) {
    int i = blockIdx.x * blockDim.x + threadIdx.x;
    if (i < E) atomicAdd(&deg[dst[i]], 1);
}
__global__ void scan_block(const int* __restrict__ deg, int* __restrict__ incl,
                           int* __restrict__ bsum, int n) {
    __shared__ int sh[256];
    int tid = threadIdx.x;
    int i = blockIdx.x * 256 + tid;
    int v = (i < n) ? deg[i] : 0;
    sh[tid] = v;
    __syncthreads();
    #pragma unroll
    for (int off = 1; off < 256; off <<= 1) {
        int t = (tid >= off) ? sh[tid - off] : 0;
        __syncthreads();
        sh[tid] += t;
        __syncthreads();
    }
    if (i < n) incl[i] = sh[tid];
    if (tid == 255) bsum[blockIdx.x] = sh[255];
}
__global__ void finalize_rowptr(const int* __restrict__ incl, const int* __restrict__ bsum,
                                int* __restrict__ rowptr, int n, int nb) {
    __shared__ int sb[256];
    int tid = threadIdx.x;
    int v = (tid < nb) ? bsum[tid] : 0;
    sb[tid] = v;
    __syncthreads();
    #pragma unroll
    for (int off = 1; off < 256; off <<= 1) {
        int t = (tid >= off) ? sb[tid - off] : 0;
        __syncthreads();
        sb[tid] += t;
        __syncthreads();
    }
    int excl = sb[tid] - v;
    __syncthreads();
    sb[tid] = excl;
    __syncthreads();
    int i = blockIdx.x * blockDim.x + tid;
    if (i < n) rowptr[i + 1] = incl[i] + sb[blockIdx.x];
    if (i == 0) rowptr[0] = 0;
}
__global__ void scatter_edges(const int* __restrict__ src, const int* __restrict__ dst,
                              const int* __restrict__ rowptr, int* __restrict__ fill,
                              int* __restrict__ csrc, int E) {
    int i = blockIdx.x * blockDim.x + threadIdx.x;
    if (i >= E) return;
    int d = dst[i];
    int pos = rowptr[d] + atomicAdd(&fill[d], 1);
    csrc[pos] = src[i];
}

// ================= fp32 -> bf16 hi/lo split (input x only) =================
__global__ void split_rows(const float* __restrict__ src, __nv_bfloat16* __restrict__ hi,
                           __nv_bfloat16* __restrict__ lo, int nvalid) {
    int i = blockIdx.x * blockDim.x + threadIdx.x;
    if (i >= MPAD * DIM) return;
    float v = (i < nvalid) ? src[i] : 0.f;
    __nv_bfloat16 h = __float2bfloat16(v);
    hi[i] = h;
    lo[i] = __float2bfloat16(v - __bfloat162float(h));
}

// all three layers' weight transposes + splits in one kernel
__global__ void transpose_all(const float* __restrict__ W0, const float* __restrict__ W1,
                              const float* __restrict__ W2, const float* __restrict__ Wr,
                              __nv_bfloat16* __restrict__ bh0, __nv_bfloat16* __restrict__ bl0,
                              __nv_bfloat16* __restrict__ bh1, __nv_bfloat16* __restrict__ bl1,
                              __nv_bfloat16* __restrict__ bh2, __nv_bfloat16* __restrict__ bl2) {
    int i = blockIdx.x * blockDim.x + threadIdx.x;
    if (i < 65536) {
        int k = i >> 8, n = i & 255;
        float v = W0[k * 256 + n];
        __nv_bfloat16 h = __float2bfloat16(v);
        bh0[n * 256 + k] = h;
        bl0[n * 256 + k] = __float2bfloat16(v - __bfloat162float(h));
    } else if (i < 131072) {
        int j = i - 65536;
        int k = j >> 8, n = j & 255;
        float v = W1[k * 256 + n];
        __nv_bfloat16 h = __float2bfloat16(v);
        bh1[n * 256 + k] = h;
        bl1[n * 256 + k] = __float2bfloat16(v - __bfloat162float(h));
    } else if (i < 147456) {
        int j = i - 131072;
        int n = j >> 8, k = j & 255;
        float v = (n < 32) ? W2[k * 32 + n] : Wr[k * 32 + (n - 32)];
        __nv_bfloat16 h = __float2bfloat16(v);
        bh2[n * 256 + k] = h;
        bl2[n * 256 + k] = __float2bfloat16(v - __bfloat162float(h));
    }
}

// ================= mma.sync bf16x3 GEMM — 3-stage cp.async pipeline =================
template<int BN, int NT, bool SPLITOUT>
__global__ void __launch_bounds__(256, 2)
gemm_mma(const __nv_bfloat16* __restrict__ Ahi, const __nv_bfloat16* __restrict__ Alo,
         const __nv_bfloat16* __restrict__ Bhi, const __nv_bfloat16* __restrict__ Blo,
         float* __restrict__ C, float* __restrict__ C2, int M)
{
    constexpr int ACH = 1024;
    constexpr int BCH = BN * 8;
    constexpr int STAGE = 16384 + BN * 128;
    extern __shared__ char smem[];
    const uint32_t sbase = smem_u32(smem);
    const int tid  = threadIdx.x;
    const int wid  = tid >> 5;
    const int lane = tid & 31;
    const int rowBase = blockIdx.y * 128;
    const int colBase = blockIdx.x * BN;
    const int m0w = (wid & 1) * 64;
    const int n0w = (wid >> 1) * (NT * 8);

    float acc[4][NT][4];
    #pragma unroll
    for (int i = 0; i < 4; i++)
        #pragma unroll
        for (int j = 0; j < NT; j++)
            #pragma unroll
            for (int q = 0; q < 4; q++) acc[i][j][q] = 0.f;

    auto load_stage = [&](int s, int buf) {
        const int k0 = s * 32;
        const uint32_t ab = sbase + buf * STAGE;
        const uint32_t bb = ab + 16384;
        #pragma unroll
        for (int c = tid; c < ACH + BCH; c += 256) {
            if (c < ACH) {
                int row = c >> 3, sub = c & 7;
                const __nv_bfloat16* g = (sub < 4)
                    ? Ahi + ((size_t)(rowBase + row) << 8) + k0 + sub * 8
                    : Alo + ((size_t)(rowBase + row) << 8) + k0 + (sub - 4) * 8;
                CP_ASYNC16(ab + swz(row * 128 + sub * 16), g);
            } else {
                int bc = c - ACH;
                int row = bc >> 3, sub = bc & 7;
                const __nv_bfloat16* g = (sub < 4)
                    ? Bhi + ((size_t)(colBase + row) << 8) + k0 + sub * 8
                    : Blo + ((size_t)(colBase + row) << 8) + k0 + (sub - 4) * 8;
                CP_ASYNC16(bb + swz(row * 128 + sub * 16), g);
            }
        }
        CP_COMMIT();
    };

    load_stage(0, 0);
    load_stage(1, 1);
    load_stage(2, 2);

    const int aRow = (lane & 15);
    const int aColX = (lane >> 4) << 4;
    const int bRowX = (lane & 7) + ((lane & 16) ? 8 : 0);
    const int bColX = (lane & 8) ? 16 : 0;

    #pragma unroll
    for (int s = 0; s < 8; s++) {
        if (s <= 5)      asm volatile("cp.async.wait_group 2;" ::: "memory");
        else if (s == 6) asm volatile("cp.async.wait_group 1;" ::: "memory");
        else             asm volatile("cp.async.wait_group 0;" ::: "memory");
        __syncthreads();
        const uint32_t ab = sbase + (s % 3) * STAGE;
        const uint32_t bb = ab + 16384;
        #pragma unroll
        for (int kk = 0; kk < 2; kk++) {
            const int ckh = kk * 32;
            const int ckl = 64 + kk * 32;
            uint32_t ar[4][4], bh[NT / 2][4], bl[NT / 2][4];
            #pragma unroll
            for (int mt = 0; mt < 4; mt++) {
                int row = m0w + mt * 16 + aRow;
                ldm_x4(ar[mt], ab + swz(row * 128 + ckh + aColX));
            }
            #pragma unroll
            for (int bt = 0; bt < NT / 2; bt++) {
                int row = n0w + bt * 16 + bRowX;
                ldm_x4(bh[bt], bb + swz(row * 128 + ckh + bColX));
                ldm_x4(bl[bt], bb + swz(row * 128 + ckl + bColX));
            }
            #pragma unroll
            for (int mt = 0; mt < 4; mt++)
                #pragma unroll
                for (int nt = 0; nt < NT; nt++) {
                    mma16816(acc[mt][nt], ar[mt], &bh[nt >> 1][(nt & 1) * 2]);
                    mma16816(acc[mt][nt], ar[mt], &bl[nt >> 1][(nt & 1) * 2]);
                }
            #pragma unroll
            for (int mt = 0; mt < 4; mt++) {
                int row = m0w + mt * 16 + aRow;
                ldm_x4(ar[mt], ab + swz(row * 128 + ckl + aColX));
            }
            #pragma unroll
            for (int mt = 0; mt < 4; mt++)
                #pragma unroll
                for (int nt = 0; nt < NT; nt++)
                    mma16816(acc[mt][nt], ar[mt], &bh[nt >> 1][(nt & 1) * 2]);
        }
        __syncthreads();
        if (s + 3 < 8) load_stage(s + 3, s % 3);
    }

    const int g = lane >> 2, tg = lane & 3;
    #pragma unroll
    for (int mt = 0; mt < 4; mt++) {
        int row0 = rowBase + m0w + mt * 16 + g;
        #pragma unroll
        for (int nt = 0; nt < NT; nt++) {
            int col = n0w + nt * 8 + tg * 2;
            if (!SPLITOUT) {
                int gc = colBase + col;
                if (row0 < M)
                    *(float2*)(C + (size_t)row0 * DIM + gc) = make_float2(acc[mt][nt][0], acc[mt][nt][1]);
                if (row0 + 8 < M)
                    *(float2*)(C + (size_t)(row0 + 8) * DIM + gc) = make_float2(acc[mt][nt][2], acc[mt][nt][3]);
            } else {
                float* base0 = (col < 32) ? C : C2;
                int cc = (col < 32) ? col : col - 32;
                if (row0 < M)
                    *(float2*)(base0 + (size_t)row0 * COUT + cc) = make_float2(acc[mt][nt][0], acc[mt][nt][1]);
                if (row0 + 8 < M)
                    *(float2*)(base0 + (size_t)(row0 + 8) * COUT + cc) = make_float2(acc[mt][nt][2], acc[mt][nt][3]);
            }
        }
    }
}

// ================= fused GATv2 edge layer (H=4, D=64), warp per node =================
// online softmax; epilogue: /z, [+res fp32], elu, [fp32 out], bf16 hi/lo pair via
// ELEMENT-WISE typed stores (mirrors split_rows exactly — no type punning).
template<bool HASRES, bool WF32>
__global__ void __launch_bounds__(256)
gat_layer_h4(const float* __restrict__ f, const int* __restrict__ rowptr,
             const int* __restrict__ csrc, const float* __restrict__ a,
             const float* __restrict__ resF, float* __restrict__ outF,
             __nv_bfloat16* __restrict__ outHi, __nv_bfloat16* __restrict__ outLo, int n) {
    int warp = (blockIdx.x * blockDim.x + threadIdx.x) >> 5;
    int lane = threadIdx.x & 31;
    if (warp >= n) return;
    const int node = warp;
    const int base = lane * 8;

    float ar[8], fd[8];
    {
        float4 t0 = __ldg((const float4*)(a + base));
        float4 t1 = __ldg((const float4*)(a + base + 4));
        ar[0]=t0.x; ar[1]=t0.y; ar[2]=t0.z; ar[3]=t0.w;
        ar[4]=t1.x; ar[5]=t1.y; ar[6]=t1.z; ar[7]=t1.w;
        const float4* fp = (const float4*)(f + (size_t)node * DIM + base);
        float4 d0 = fp[0], d1 = fp[1];
        fd[0]=d0.x; fd[1]=d0.y; fd[2]=d0.z; fd[3]=d0.w;
        fd[4]=d1.x; fd[5]=d1.y; fd[6]=d1.z; fd[7]=d1.w;
    }

    float acc[8] = {0,0,0,0,0,0,0,0};
    float m = NEGINF, s = 0.f;

    int e0 = rowptr[node], e1 = rowptr[node + 1];
    float4 c0, c1v, p0, p1v;
    {
        int s0 = csrc[e0];
        const float4* fp = (const float4*)(f + (size_t)s0 * DIM + base);
        c0 = fp[0]; c1v = fp[1];
    }
    if (e0 + 1 < e1) {
        int s1 = csrc[e0 + 1];
        const float4* fp = (const float4*)(f + (size_t)s1 * DIM + base);
        p0 = fp[0]; p1v = fp[1];
    }
    for (int e = e0; e < e1; e++) {
        float u[8] = {c0.x, c0.y, c0.z, c0.w, c1v.x, c1v.y, c1v.z, c1v.w};
        c0 = p0; c1v = p1v;
        if (e + 2 < e1) {
            int ns = csrc[e + 2];
            const float4* fp = (const float4*)(f + (size_t)ns * DIM + base);
            p0 = fp[0]; p1v = fp[1];
        }
        float p = 0.f;
        #pragma unroll
        for (int j = 0; j < 8; j++) {
            float v = u[j] + fd[j];
            float lv = v > 0.f ? v : 0.2f * v;
            p = fmaf(lv, ar[j], p);
        }
        p += __shfl_xor_sync(0xffffffffu, p, 1);
        p += __shfl_xor_sync(0xffffffffu, p, 2);
        p += __shfl_xor_sync(0xffffffffu, p, 4);

        float mn = fmaxf(m, p);
        float sc1 = __expf(m - mn);
        float sc2 = __expf(p - mn);
        s = s * sc1 + sc2;
        #pragma unroll
        for (int j = 0; j < 8; j++)
            acc[j] = fmaf(acc[j], sc1, sc2 * u[j]);
        m = mn;
    }
    float inv = 1.0f / s;
    float o[8];
    size_t oidx = (size_t)node * DIM + base;
    #pragma unroll
    for (int j = 0; j < 8; j++) o[j] = acc[j] * inv;
    if (HASRES) {
        const float4* rp = (const float4*)(resF + oidx);
        float4 r0 = rp[0], r1 = rp[1];
        o[0]+=r0.x; o[1]+=r0.y; o[2]+=r0.z; o[3]+=r0.w;
        o[4]+=r1.x; o[5]+=r1.y; o[6]+=r1.z; o[7]+=r1.w;
    }
    #pragma unroll
    for (int j = 0; j < 8; j++) o[j] = o[j] > 0.f ? o[j] : expm1f(o[j]);
    if (WF32) {
        float4* op = (float4*)(outF + oidx);
        op[0] = make_float4(o[0], o[1], o[2], o[3]);
        op[1] = make_float4(o[4], o[5], o[6], o[7]);
    }
    // bf16 hi/lo split — element-wise, typed, exactly like split_rows
    #pragma unroll
    for (int j = 0; j < 8; j++) {
        float v = o[j];
        __nv_bfloat16 h = __float2bfloat16(v);
        outHi[oidx + j] = h;
        outLo[oidx + j] = __float2bfloat16(v - __bfloat162float(h));
    }
}

// ================= fused final layer (H=1, D=32), warp per node =================
__global__ void __launch_bounds__(256)
gat_layer_h1(const float* __restrict__ f2, const int* __restrict__ rowptr,
             const int* __restrict__ csrc, const float* __restrict__ a,
             const float* __restrict__ r2, float* __restrict__ out, int n) {
    int warp = (blockIdx.x * blockDim.x + threadIdx.x) >> 5;
    int lane = threadIdx.x & 31;
    if (warp >= n) return;
    const int node = warp;

    float ar = __ldg(a + lane);
    float fd = f2[(size_t)node * COUT + lane];

    float acc = 0.f, m = NEGINF, s = 0.f;
    int e0 = rowptr[node], e1 = rowptr[node + 1];
    float cur = f2[(size_t)csrc[e0] * COUT + lane];
    float nxt = 0.f;
    if (e0 + 1 < e1) nxt = f2[(size_t)csrc[e0 + 1] * COUT + lane];
    for (int e = e0; e < e1; e++) {
        float u = cur;
        cur = nxt;
        if (e + 2 < e1) nxt = f2[(size_t)csrc[e + 2] * COUT + lane];
        float v = u + fd;
        float lv = v > 0.f ? v : 0.2f * v;
        float p = lv * ar;
        p += __shfl_xor_sync(0xffffffffu, p, 1);
        p += __shfl_xor_sync(0xffffffffu, p, 2);
        p += __shfl_xor_sync(0xffffffffu, p, 4);
        p += __shfl_xor_sync(0xffffffffu, p, 8);
        p += __shfl_xor_sync(0xffffffffu, p, 16);
        float mn = fmaxf(m, p);
        float sc1 = __expf(m - mn);
        float sc2 = __expf(p - mn);
        s = s * sc1 + sc2;
        acc = fmaf(acc, sc1, sc2 * u);
        m = mn;
    }
    out[(size_t)node * COUT + lane] = acc / s + r2[(size_t)node * COUT + lane];
}

// ================= host =================
extern "C" void kernel_launch(void* const* d_in, const int* in_sizes, int n_in,
                              void* d_out, int out_size) {
    const float* x     = (const float*)d_in[0];
    const int*   src   = (const int*)  d_in[1];
    const int*   dst   = (const int*)  d_in[2];
    const float* W0    = (const float*)d_in[3];
    const float* a0    = (const float*)d_in[4];
    const float* W1    = (const float*)d_in[5];
    const float* a1    = (const float*)d_in[6];
    const float* W2    = (const float*)d_in[7];
    const float* a2    = (const float*)d_in[8];
    const float* Wres2 = (const float*)d_in[9];
    int E = in_sizes[1];
    if (E > EMAX) E = EMAX;

    float *f, *h0, *f2, *r2;
    __nv_bfloat16 *ahi, *alo, *bh0, *bl0, *bh1, *bl1, *bh2, *bl2;
    int *deg, *fill, *tmp, *bsum, *rowptr, *csrc;
    cudaGetSymbolAddress((void**)&f,    g_f);
    cudaGetSymbolAddress((void**)&h0,   g_h0);
    cudaGetSymbolAddress((void**)&f2,   g_f2);
    cudaGetSymbolAddress((void**)&r2,   g_r2);
    cudaGetSymbolAddress((void**)&ahi,  g_ahi);
    cudaGetSymbolAddress((void**)&alo,  g_alo);
    cudaGetSymbolAddress((void**)&bh0,  g_bh0);
    cudaGetSymbolAddress((void**)&bl0,  g_bl0);
    cudaGetSymbolAddress((void**)&bh1,  g_bh1);
    cudaGetSymbolAddress((void**)&bl1,  g_bl1);
    cudaGetSymbolAddress((void**)&bh2,  g_bh2);
    cudaGetSymbolAddress((void**)&bl2,  g_bl2);
    cudaGetSymbolAddress((void**)&deg,  g_deg);
    cudaGetSymbolAddress((void**)&fill, g_fill);
    cudaGetSymbolAddress((void**)&tmp,  g_tmp);
    cudaGetSymbolAddress((void**)&bsum, g_bsum);
    cudaGetSymbolAddress((void**)&rowptr, g_rowptr);
    cudaGetSymbolAddress((void**)&csrc, g_csrc);

    const int SMEM_BIG   = 3 * (16384 + 128 * 128);  // 98304
    const int SMEM_SMALL = 3 * (16384 + 64 * 128);   // 73728
    static int inited = 0;
    static cudaStream_t s2;
    static cudaEvent_t evFork, evJoin;
    if (!inited) {
        cudaFuncSetAttribute((const void*)gemm_mma<128, 4, false>,
                             cudaFuncAttributeMaxDynamicSharedMemorySize, SMEM_BIG);
        cudaFuncSetAttribute((const void*)gemm_mma<64, 2, true>,
                             cudaFuncAttributeMaxDynamicSharedMemorySize, SMEM_SMALL);
        cudaStreamCreateWithFlags(&s2, cudaStreamNonBlocking);
        cudaEventCreateWithFlags(&evFork, cudaEventDisableTiming);
        cudaEventCreateWithFlags(&evJoin, cudaEventDisableTiming);
        inited = 1;
    }

    const int TPB = 256;
    const int NB = (NNODES + 255) / 256;   // 196
    const int EB = (E + TPB - 1) / TPB;
    const int nodeWarpBlocks = (NNODES * 32 + TPB - 1) / TPB;
    const int splitBlocks = (MPAD * DIM + TPB - 1) / TPB;
    dim3 gemmGrid(2, MPAD / 128);
    dim3 gemmGridS(1, MPAD / 128);

    // ---- fork: CSR build chain runs on s2, concurrent with split/transpose/GEMM-0 ----
    cudaEventRecord(evFork, 0);
    cudaStreamWaitEvent(s2, evFork, 0);
    zero_ints<<<NB, TPB, 0, s2>>>(deg, fill, NNODES);
    hist_deg<<<EB, TPB, 0, s2>>>(dst, deg, E);
    scan_block<<<NB, TPB, 0, s2>>>(deg, tmp, bsum, NNODES);
    finalize_rowptr<<<NB, TPB, 0, s2>>>(tmp, bsum, rowptr, NNODES, NB);
    scatter_edges<<<EB, TPB, 0, s2>>>(src, dst, rowptr, fill, csrc, E);
    cudaEventRecord(evJoin, s2);

    // ---- main stream: layer-0 projection ----
    split_rows<<<splitBlocks, TPB>>>(x, ahi, alo, NNODES * DIM);
    transpose_all<<<(147456 + TPB - 1) / TPB, TPB>>>(W0, W1, W2, Wres2,
                                                     bh0, bl0, bh1, bl1, bh2, bl2);
    gemm_mma<128, 4, false><<<gemmGrid, TPB, SMEM_BIG>>>(ahi, alo, bh0, bl0, f, nullptr, NNODES);

    // ---- join: GAT needs CSR + f ----
    cudaStreamWaitEvent(0, evJoin, 0);
    // layer 0: writes fp32 h0 (residual) + bf16 pair (next GEMM input)
    gat_layer_h4<false, true><<<nodeWarpBlocks, TPB>>>(f, rowptr, csrc, a0,
                                                       nullptr, h0, ahi, alo, NNODES);

    // ---- layer 1 ----
    gemm_mma<128, 4, false><<<gemmGrid, TPB, SMEM_BIG>>>(ahi, alo, bh1, bl1, f, nullptr, NNODES);
    gat_layer_h4<true, false><<<nodeWarpBlocks, TPB>>>(f, rowptr, csrc, a1,
                                                       h0, nullptr, ahi, alo, NNODES);

    // ---- layer 2 ----
    gemm_mma<64, 2, true><<<gemmGridS, TPB, SMEM_SMALL>>>(ahi, alo, bh2, bl2, f2, r2, NNODES);
    gat_layer_h1<<<nodeWarpBlocks, TPB>>>(f2, rowptr, csrc, a2, r2, (float*)d_out, NNODES);
}

// round 12
// speedup vs baseline: 1.1611x; 1.0082x over previous
#include <cuda_runtime.h>
#include <cuda_bf16.h>
#include <math.h>
#include <stdint.h>

#define NNODES 50000
#define MPAD   50048            // 391 * 128
#define EMAX   850048
#define DIM    256
#define COUT   32
#define NEGINF __int_as_float(0xff800000)

// ---------------- scratch (device globals; no allocation allowed) ----------------
__device__ __align__(128) float g_f  [NNODES * DIM];
__device__ __align__(128) float g_f2 [NNODES * COUT];
__device__ __align__(128) float g_r2 [NNODES * COUT];
__device__ __align__(128) __nv_bfloat16 g_ahi[(size_t)MPAD * DIM];
__device__ __align__(128) __nv_bfloat16 g_alo[(size_t)MPAD * DIM];
__device__ __align__(128) __nv_bfloat16 g_bh0[DIM * DIM];
__device__ __align__(128) __nv_bfloat16 g_bl0[DIM * DIM];
__device__ __align__(128) __nv_bfloat16 g_bh1[DIM * DIM];
__device__ __align__(128) __nv_bfloat16 g_bl1[DIM * DIM];
__device__ __align__(128) __nv_bfloat16 g_bh2[64 * DIM];
__device__ __align__(128) __nv_bfloat16 g_bl2[64 * DIM];
__device__ __align__(128) int   g_deg [NNODES];
__device__ __align__(128) int   g_fill[NNODES];
__device__ __align__(128) int   g_tmp [NNODES];
__device__ __align__(128) int   g_bsum[256];
__device__ __align__(128) int   g_rowptr[NNODES + 1];
__device__ __align__(128) int   g_csrc[EMAX];

// ================= helpers =================
__device__ __forceinline__ uint32_t smem_u32(const void* p) {
    uint32_t a;
    asm("{ .reg .u64 t; cvta.to.shared.u64 t, %1; cvt.u32.u64 %0, t; }" : "=r"(a) : "l"(p));
    return a;
}
__device__ __forceinline__ uint32_t swz(uint32_t off) {
    return off ^ ((off >> 3) & 0x70);   // SW128 for 128B rows
}
#define CP_ASYNC16(dst, src) \
    asm volatile("cp.async.cg.shared.global [%0], [%1], 16;" :: "r"(dst), "l"(src) : "memory")
#define CP_COMMIT()  asm volatile("cp.async.commit_group;" ::: "memory")

__device__ __forceinline__ void ldm_x4(uint32_t* r, uint32_t addr) {
    asm volatile("ldmatrix.sync.aligned.m8n8.x4.shared.b16 {%0,%1,%2,%3}, [%4];"
                 : "=r"(r[0]), "=r"(r[1]), "=r"(r[2]), "=r"(r[3]) : "r"(addr));
}
__device__ __forceinline__ void mma16816(float* d, const uint32_t* a, const uint32_t* b) {
    asm volatile("mma.sync.aligned.m16n8k16.row.col.f32.bf16.bf16.f32 "
                 "{%0,%1,%2,%3}, {%4,%5,%6,%7}, {%8,%9}, {%0,%1,%2,%3};"
                 : "+f"(d[0]), "+f"(d[1]), "+f"(d[2]), "+f"(d[3])
                 : "r"(a[0]), "r"(a[1]), "r"(a[2]), "r"(a[3]), "r"(b[0]), "r"(b[1]));
}

// ================= CSR build =================
__global__ void zero_ints(int* __restrict__ a, int* __restrict__ b, int n) {
    int i = blockIdx.x * blockDim.x + threadIdx.x;
    if (i < n) { a[i] = 0; b[i] = 0; }
}
__global__ void hist_deg(const int* __restrict__ dst, int* __restrict__ deg, int E) {
    int i = blockIdx.x * blockDim.x + threadIdx.x;
    if (i < E) atomicAdd(&deg[dst[i]], 1);
}
__global__ void scan_block(const int* __restrict__ deg, int* __restrict__ incl,
                           int* __restrict__ bsum, int n) {
    __shared__ int sh[256];
    int tid = threadIdx.x;
    int i = blockIdx.x * 256 + tid;
    int v = (i < n) ? deg[i] : 0;
    sh[tid] = v;
    __syncthreads();
    #pragma unroll
    for (int off = 1; off < 256; off <<= 1) {
        int t = (tid >= off) ? sh[tid - off] : 0;
        __syncthreads();
        sh[tid] += t;
        __syncthreads();
    }
    if (i < n) incl[i] = sh[tid];
    if (tid == 255) bsum[blockIdx.x] = sh[255];
}
__global__ void finalize_rowptr(const int* __restrict__ incl, const int* __restrict__ bsum,
                                int* __restrict__ rowptr, int n, int nb) {
    __shared__ int sb[256];
    int tid = threadIdx.x;
    int v = (tid < nb) ? bsum[tid] : 0;
    sb[tid] = v;
    __syncthreads();
    #pragma unroll
    for (int off = 1; off < 256; off <<= 1) {
        int t = (tid >= off) ? sb[tid - off] : 0;
        __syncthreads();
        sb[tid] += t;
        __syncthreads();
    }
    int excl = sb[tid] - v;
    __syncthreads();
    sb[tid] = excl;
    __syncthreads();
    int i = blockIdx.x * blockDim.x + tid;
    if (i < n) rowptr[i + 1] = incl[i] + sb[blockIdx.x];
    if (i == 0) rowptr[0] = 0;
}
__global__ void scatter_edges(const int* __restrict__ src, const int* __restrict__ dst,
                              const int* __restrict__ rowptr, int* __restrict__ fill,
                              int* __restrict__ csrc, int E) {
    int i = blockIdx.x * blockDim.x + threadIdx.x;
    if (i >= E) return;
    int d = dst[i];
    int pos = rowptr[d] + atomicAdd(&fill[d], 1);
    csrc[pos] = src[i];
}

// ================= fused prep: split(x) + all weight transposes =================
__global__ void prep_all(const float* __restrict__ x,
                         __nv_bfloat16* __restrict__ ahi, __nv_bfloat16* __restrict__ alo,
                         int nvalid,
                         const float* __restrict__ W0, const float* __restrict__ W1,
                         const float* __restrict__ W2, const float* __restrict__ Wr,
                         __nv_bfloat16* __restrict__ bh0, __nv_bfloat16* __restrict__ bl0,
                         __nv_bfloat16* __restrict__ bh1, __nv_bfloat16* __restrict__ bl1,
                         __nv_bfloat16* __restrict__ bh2, __nv_bfloat16* __restrict__ bl2) {
    const int splitBlocks = (MPAD * DIM) / 256;   // 50048
    if ((int)blockIdx.x < splitBlocks) {
        int i = blockIdx.x * 256 + threadIdx.x;
        float v = (i < nvalid) ? x[i] : 0.f;
        __nv_bfloat16 h = __float2bfloat16(v);
        ahi[i] = h;
        alo[i] = __float2bfloat16(v - __bfloat162float(h));
    } else {
        int i = (blockIdx.x - splitBlocks) * 256 + threadIdx.x;
        if (i < 65536) {
            int k = i >> 8, n = i & 255;
            float v = W0[k * 256 + n];
            __nv_bfloat16 h = __float2bfloat16(v);
            bh0[n * 256 + k] = h;
            bl0[n * 256 + k] = __float2bfloat16(v - __bfloat162float(h));
        } else if (i < 131072) {
            int j = i - 65536;
            int k = j >> 8, n = j & 255;
            float v = W1[k * 256 + n];
            __nv_bfloat16 h = __float2bfloat16(v);
            bh1[n * 256 + k] = h;
            bl1[n * 256 + k] = __float2bfloat16(v - __bfloat162float(h));
        } else if (i < 147456) {
            int j = i - 131072;
            int n = j >> 8, k = j & 255;
            float v = (n < 32) ? W2[k * 32 + n] : Wr[k * 32 + (n - 32)];
            __nv_bfloat16 h = __float2bfloat16(v);
            bh2[n * 256 + k] = h;
            bl2[n * 256 + k] = __float2bfloat16(v - __bfloat162float(h));
        }
    }
}

// ================= mma.sync bf16x3 GEMM — 3-stage cp.async pipeline =================
template<int BN, int NT, bool SPLITOUT>
__global__ void __launch_bounds__(256, 2)
gemm_mma(const __nv_bfloat16* __restrict__ Ahi, const __nv_bfloat16* __restrict__ Alo,
         const __nv_bfloat16* __restrict__ Bhi, const __nv_bfloat16* __restrict__ Blo,
         float* __restrict__ C, float* __restrict__ C2, int M)
{
    constexpr int ACH = 1024;
    constexpr int BCH = BN * 8;
    constexpr int STAGE = 16384 + BN * 128;
    extern __shared__ char smem[];
    const uint32_t sbase = smem_u32(smem);
    const int tid  = threadIdx.x;
    const int wid  = tid >> 5;
    const int lane = tid & 31;
    const int rowBase = blockIdx.y * 128;
    const int colBase = blockIdx.x * BN;
    const int m0w = (wid & 1) * 64;
    const int n0w = (wid >> 1) * (NT * 8);

    float acc[4][NT][4];
    #pragma unroll
    for (int i = 0; i < 4; i++)
        #pragma unroll
        for (int j = 0; j < NT; j++)
            #pragma unroll
            for (int q = 0; q < 4; q++) acc[i][j][q] = 0.f;

    auto load_stage = [&](int s, int buf) {
        const int k0 = s * 32;
        const uint32_t ab = sbase + buf * STAGE;
        const uint32_t bb = ab + 16384;
        #pragma unroll
        for (int c = tid; c < ACH + BCH; c += 256) {
            if (c < ACH) {
                int row = c >> 3, sub = c & 7;
                const __nv_bfloat16* g = (sub < 4)
                    ? Ahi + ((size_t)(rowBase + row) << 8) + k0 + sub * 8
                    : Alo + ((size_t)(rowBase + row) << 8) + k0 + (sub - 4) * 8;
                CP_ASYNC16(ab + swz(row * 128 + sub * 16), g);
            } else {
                int bc = c - ACH;
                int row = bc >> 3, sub = bc & 7;
                const __nv_bfloat16* g = (sub < 4)
                    ? Bhi + ((size_t)(colBase + row) << 8) + k0 + sub * 8
                    : Blo + ((size_t)(colBase + row) << 8) + k0 + (sub - 4) * 8;
                CP_ASYNC16(bb + swz(row * 128 + sub * 16), g);
            }
        }
        CP_COMMIT();
    };

    load_stage(0, 0);
    load_stage(1, 1);
    load_stage(2, 2);

    const int aRow = (lane & 15);
    const int aColX = (lane >> 4) << 4;
    const int bRowX = (lane & 7) + ((lane & 16) ? 8 : 0);
    const int bColX = (lane & 8) ? 16 : 0;

    #pragma unroll
    for (int s = 0; s < 8; s++) {
        if (s <= 5)      asm volatile("cp.async.wait_group 2;" ::: "memory");
        else if (s == 6) asm volatile("cp.async.wait_group 1;" ::: "memory");
        else             asm volatile("cp.async.wait_group 0;" ::: "memory");
        __syncthreads();
        const uint32_t ab = sbase + (s % 3) * STAGE;
        const uint32_t bb = ab + 16384;
        #pragma unroll
        for (int kk = 0; kk < 2; kk++) {
            const int ckh = kk * 32;
            const int ckl = 64 + kk * 32;
            uint32_t ar[4][4], bh[NT / 2][4], bl[NT / 2][4];
            #pragma unroll
            for (int mt = 0; mt < 4; mt++) {
                int row = m0w + mt * 16 + aRow;
                ldm_x4(ar[mt], ab + swz(row * 128 + ckh + aColX));
            }
            #pragma unroll
            for (int bt = 0; bt < NT / 2; bt++) {
                int row = n0w + bt * 16 + bRowX;
                ldm_x4(bh[bt], bb + swz(row * 128 + ckh + bColX));
                ldm_x4(bl[bt], bb + swz(row * 128 + ckl + bColX));
            }
            #pragma unroll
            for (int mt = 0; mt < 4; mt++)
                #pragma unroll
                for (int nt = 0; nt < NT; nt++) {
                    mma16816(acc[mt][nt], ar[mt], &bh[nt >> 1][(nt & 1) * 2]);
                    mma16816(acc[mt][nt], ar[mt], &bl[nt >> 1][(nt & 1) * 2]);
                }
            #pragma unroll
            for (int mt = 0; mt < 4; mt++) {
                int row = m0w + mt * 16 + aRow;
                ldm_x4(ar[mt], ab + swz(row * 128 + ckl + aColX));
            }
            #pragma unroll
            for (int mt = 0; mt < 4; mt++)
                #pragma unroll
                for (int nt = 0; nt < NT; nt++)
                    mma16816(acc[mt][nt], ar[mt], &bh[nt >> 1][(nt & 1) * 2]);
        }
        __syncthreads();
        if (s + 3 < 8) load_stage(s + 3, s % 3);
    }

    const int g = lane >> 2, tg = lane & 3;
    #pragma unroll
    for (int mt = 0; mt < 4; mt++) {
        int row0 = rowBase + m0w + mt * 16 + g;
        #pragma unroll
        for (int nt = 0; nt < NT; nt++) {
            int col = n0w + nt * 8 + tg * 2;
            if (!SPLITOUT) {
                int gc = colBase + col;
                if (row0 < M)
                    *(float2*)(C + (size_t)row0 * DIM + gc) = make_float2(acc[mt][nt][0], acc[mt][nt][1]);
                if (row0 + 8 < M)
                    *(float2*)(C + (size_t)(row0 + 8) * DIM + gc) = make_float2(acc[mt][nt][2], acc[mt][nt][3]);
            } else {
                float* base0 = (col < 32) ? C : C2;
                int cc = (col < 32) ? col : col - 32;
                if (row0 < M)
                    *(float2*)(base0 + (size_t)row0 * COUT + cc) = make_float2(acc[mt][nt][0], acc[mt][nt][1]);
                if (row0 + 8 < M)
                    *(float2*)(base0 + (size_t)(row0 + 8) * COUT + cc) = make_float2(acc[mt][nt][2], acc[mt][nt][3]);
            }
        }
    }
}

// ================= fused GATv2 edge layer (H=4, D=64), warp per node =================
// online softmax; epilogue: /z, [+res = hi+lo of own pair], elu, write bf16 pair.
template<bool HASRES>
__global__ void __launch_bounds__(256)
gat_layer_h4(const float* __restrict__ f, const int* __restrict__ rowptr,
             const int* __restrict__ csrc, const float* __restrict__ a,
             __nv_bfloat16* __restrict__ outHi, __nv_bfloat16* __restrict__ outLo, int n) {
    int warp = (blockIdx.x * blockDim.x + threadIdx.x) >> 5;
    int lane = threadIdx.x & 31;
    if (warp >= n) return;
    const int node = warp;
    const int base = lane * 8;

    float ar[8], fd[8];
    {
        float4 t0 = __ldg((const float4*)(a + base));
        float4 t1 = __ldg((const float4*)(a + base + 4));
        ar[0]=t0.x; ar[1]=t0.y; ar[2]=t0.z; ar[3]=t0.w;
        ar[4]=t1.x; ar[5]=t1.y; ar[6]=t1.z; ar[7]=t1.w;
        const float4* fp = (const float4*)(f + (size_t)node * DIM + base);
        float4 d0 = fp[0], d1 = fp[1];
        fd[0]=d0.x; fd[1]=d0.y; fd[2]=d0.z; fd[3]=d0.w;
        fd[4]=d1.x; fd[5]=d1.y; fd[6]=d1.z; fd[7]=d1.w;
    }

    float acc[8] = {0,0,0,0,0,0,0,0};
    float m = NEGINF, s = 0.f;

    int e0 = rowptr[node], e1 = rowptr[node + 1];
    float4 c0, c1v, p0, p1v;
    {
        int s0 = csrc[e0];
        const float4* fp = (const float4*)(f + (size_t)s0 * DIM + base);
        c0 = fp[0]; c1v = fp[1];
    }
    if (e0 + 1 < e1) {
        int s1 = csrc[e0 + 1];
        const float4* fp = (const float4*)(f + (size_t)s1 * DIM + base);
        p0 = fp[0]; p1v = fp[1];
    }
    for (int e = e0; e < e1; e++) {
        float u[8] = {c0.x, c0.y, c0.z, c0.w, c1v.x, c1v.y, c1v.z, c1v.w};
        c0 = p0; c1v = p1v;
        if (e + 2 < e1) {
            int ns = csrc[e + 2];
            const float4* fp = (const float4*)(f + (size_t)ns * DIM + base);
            p0 = fp[0]; p1v = fp[1];
        }
        float p = 0.f;
        #pragma unroll
        for (int j = 0; j < 8; j++) {
            float v = u[j] + fd[j];
            float lv = v > 0.f ? v : 0.2f * v;
            p = fmaf(lv, ar[j], p);
        }
        p += __shfl_xor_sync(0xffffffffu, p, 1);
        p += __shfl_xor_sync(0xffffffffu, p, 2);
        p += __shfl_xor_sync(0xffffffffu, p, 4);

        float mn = fmaxf(m, p);
        float sc1 = __expf(m - mn);
        float sc2 = __expf(p - mn);
        s = s * sc1 + sc2;
        #pragma unroll
        for (int j = 0; j < 8; j++)
            acc[j] = fmaf(acc[j], sc1, sc2 * u[j]);
        m = mn;
    }
    float inv = 1.0f / s;
    float o[8];
    size_t oidx = (size_t)node * DIM + base;
    #pragma unroll
    for (int j = 0; j < 8; j++) o[j] = acc[j] * inv;
    if (HASRES) {
        // residual = previous layer output reconstructed from own bf16 pair
        #pragma unroll
        for (int j = 0; j < 8; j++) {
            float rh = __bfloat162float(outHi[oidx + j]);
            float rl = __bfloat162float(outLo[oidx + j]);
            o[j] += rh + rl;
        }
    }
    #pragma unroll
    for (int j = 0; j < 8; j++) o[j] = o[j] > 0.f ? o[j] : expm1f(o[j]);
    // bf16 hi/lo split — element-wise typed stores
    #pragma unroll
    for (int j = 0; j < 8; j++) {
        float v = o[j];
        __nv_bfloat16 h = __float2bfloat16(v);
        outHi[oidx + j] = h;
        outLo[oidx + j] = __float2bfloat16(v - __bfloat162float(h));
    }
}

// ================= fused final layer (H=1, D=32), warp per node =================
__global__ void __launch_bounds__(256)
gat_layer_h1(const float* __restrict__ f2, const int* __restrict__ rowptr,
             const int* __restrict__ csrc, const float* __restrict__ a,
             const float* __restrict__ r2, float* __restrict__ out, int n) {
    int warp = (blockIdx.x * blockDim.x + threadIdx.x) >> 5;
    int lane = threadIdx.x & 31;
    if (warp >= n) return;
    const int node = warp;

    float ar = __ldg(a + lane);
    float fd = f2[(size_t)node * COUT + lane];

    float acc = 0.f, m = NEGINF, s = 0.f;
    int e0 = rowptr[node], e1 = rowptr[node + 1];
    float cur = f2[(size_t)csrc[e0] * COUT + lane];
    float nxt = 0.f;
    if (e0 + 1 < e1) nxt = f2[(size_t)csrc[e0 + 1] * COUT + lane];
    for (int e = e0; e < e1; e++) {
        float u = cur;
        cur = nxt;
        if (e + 2 < e1) nxt = f2[(size_t)csrc[e + 2] * COUT + lane];
        float v = u + fd;
        float lv = v > 0.f ? v : 0.2f * v;
        float p = lv * ar;
        p += __shfl_xor_sync(0xffffffffu, p, 1);
        p += __shfl_xor_sync(0xffffffffu, p, 2);
        p += __shfl_xor_sync(0xffffffffu, p, 4);
        p += __shfl_xor_sync(0xffffffffu, p, 8);
        p += __shfl_xor_sync(0xffffffffu, p, 16);
        float mn = fmaxf(m, p);
        float sc1 = __expf(m - mn);
        float sc2 = __expf(p - mn);
        s = s * sc1 + sc2;
        acc = fmaf(acc, sc1, sc2 * u);
        m = mn;
    }
    out[(size_t)node * COUT + lane] = acc / s + r2[(size_t)node * COUT + lane];
}

// ================= host =================
extern "C" void kernel_launch(void* const* d_in, const int* in_sizes, int n_in,
                              void* d_out, int out_size) {
    const float* x     = (const float*)d_in[0];
    const int*   src   = (const int*)  d_in[1];
    const int*   dst   = (const int*)  d_in[2];
    const float* W0    = (const float*)d_in[3];
    const float* a0    = (const float*)d_in[4];
    const float* W1    = (const float*)d_in[5];
    const float* a1    = (const float*)d_in[6];
    const float* W2    = (const float*)d_in[7];
    const float* a2    = (const float*)d_in[8];
    const float* Wres2 = (const float*)d_in[9];
    int E = in_sizes[1];
    if (E > EMAX) E = EMAX;

    float *f, *f2, *r2;
    __nv_bfloat16 *ahi, *alo, *bh0, *bl0, *bh1, *bl1, *bh2, *bl2;
    int *deg, *fill, *tmp, *bsum, *rowptr, *csrc;
    cudaGetSymbolAddress((void**)&f,    g_f);
    cudaGetSymbolAddress((void**)&f2,   g_f2);
    cudaGetSymbolAddress((void**)&r2,   g_r2);
    cudaGetSymbolAddress((void**)&ahi,  g_ahi);
    cudaGetSymbolAddress((void**)&alo,  g_alo);
    cudaGetSymbolAddress((void**)&bh0,  g_bh0);
    cudaGetSymbolAddress((void**)&bl0,  g_bl0);
    cudaGetSymbolAddress((void**)&bh1,  g_bh1);
    cudaGetSymbolAddress((void**)&bl1,  g_bl1);
    cudaGetSymbolAddress((void**)&bh2,  g_bh2);
    cudaGetSymbolAddress((void**)&bl2,  g_bl2);
    cudaGetSymbolAddress((void**)&deg,  g_deg);
    cudaGetSymbolAddress((void**)&fill, g_fill);
    cudaGetSymbolAddress((void**)&tmp,  g_tmp);
    cudaGetSymbolAddress((void**)&bsum, g_bsum);
    cudaGetSymbolAddress((void**)&rowptr, g_rowptr);
    cudaGetSymbolAddress((void**)&csrc, g_csrc);

    const int SMEM_BIG   = 3 * (16384 + 128 * 128);  // 98304
    const int SMEM_SMALL = 3 * (16384 + 64 * 128);   // 73728
    static int inited = 0;
    static cudaStream_t s2;
    static cudaEvent_t evFork, evJoin;
    if (!inited) {
        cudaFuncSetAttribute((const void*)gemm_mma<128, 4, false>,
                             cudaFuncAttributeMaxDynamicSharedMemorySize, SMEM_BIG);
        cudaFuncSetAttribute((const void*)gemm_mma<64, 2, true>,
                             cudaFuncAttributeMaxDynamicSharedMemorySize, SMEM_SMALL);
        cudaStreamCreateWithFlags(&s2, cudaStreamNonBlocking);
        cudaEventCreateWithFlags(&evFork, cudaEventDisableTiming);
        cudaEventCreateWithFlags(&evJoin, cudaEventDisableTiming);
        inited = 1;
    }

    const int TPB = 256;
    const int NB = (NNODES + 255) / 256;   // 196
    const int EB = (E + TPB - 1) / TPB;
    const int nodeWarpBlocks = (NNODES * 32 + TPB - 1) / TPB;
    const int splitBlocks = (MPAD * DIM) / 256;   // 50048
    dim3 gemmGrid(2, MPAD / 128);
    dim3 gemmGridS(1, MPAD / 128);

    // ---- fork: CSR build chain runs on s2, concurrent with prep/GEMM-0 ----
    cudaEventRecord(evFork, 0);
    cudaStreamWaitEvent(s2, evFork, 0);
    zero_ints<<<NB, TPB, 0, s2>>>(deg, fill, NNODES);
    hist_deg<<<EB, TPB, 0, s2>>>(dst, deg, E);
    scan_block<<<NB, TPB, 0, s2>>>(deg, tmp, bsum, NNODES);
    finalize_rowptr<<<NB, TPB, 0, s2>>>(tmp, bsum, rowptr, NNODES, NB);
    scatter_edges<<<EB, TPB, 0, s2>>>(src, dst, rowptr, fill, csrc, E);
    cudaEventRecord(evJoin, s2);

    // ---- main stream: prep (split x + all transposes) then layer-0 GEMM ----
    prep_all<<<splitBlocks + 576, TPB>>>(x, ahi, alo, NNODES * DIM,
                                         W0, W1, W2, Wres2,
                                         bh0, bl0, bh1, bl1, bh2, bl2);
    gemm_mma<128, 4, false><<<gemmGrid, TPB, SMEM_BIG>>>(ahi, alo, bh0, bl0, f, nullptr, NNODES);

    // ---- join: GAT needs CSR + f ----
    cudaStreamWaitEvent(0, evJoin, 0);
    // layer 0: writes bf16 pair only (pair doubles as residual source for layer 1)
    gat_layer_h4<false><<<nodeWarpBlocks, TPB>>>(f, rowptr, csrc, a0, ahi, alo, NNODES);

    // ---- layer 1 ----
    gemm_mma<128, 4, false><<<gemmGrid, TPB, SMEM_BIG>>>(ahi, alo, bh1, bl1, f, nullptr, NNODES);
    gat_layer_h4<true><<<nodeWarpBlocks, TPB>>>(f, rowptr, csrc, a1, ahi, alo, NNODES);

    // ---- layer 2 ----
    gemm_mma<64, 2, true><<<gemmGridS, TPB, SMEM_SMALL>>>(ahi, alo, bh2, bl2, f2, r2, NNODES);
    gat_layer_h1<<<nodeWarpBlocks, TPB>>>(f2, rowptr, csrc, a2, r2, (float*)d_out, NNODES);
}